// round 15
// baseline (speedup 1.0000x reference)
#include <cuda_runtime.h>
#include <cuda_bf16.h>
#include <math.h>

#define BATCH 4
#define CDIM  64
#define HH    256
#define WW    256
#define HWD   65536          // H*W
#define CHROWS 16384         // C*H
#define HID   170
#define HID2  340

// ---------------- scratch (device globals; no allocations allowed) ----------------
__device__ __nv_bfloat16 g_bufA[(size_t)BATCH * CDIM * HWD];   // ln out / AV out (bf16)
__device__ float         g_bufM[(size_t)BATCH * CDIM * HWD];   // wxw output (fp32)
__device__ float         g_bufZ[(size_t)BATCH * CDIM * HWD];   // hxh output (fp32)
__device__ __nv_bfloat16 g_qkv1[(size_t)BATCH * HID2 * HWD];   // pre-dwconv qkv / ffn hidden
__device__ __nv_bfloat16 g_qkv2[(size_t)BATCH * HID2 * HWD];   // post-dwconv qkv / gated
__device__ float         g_attn[(size_t)BATCH * WW * WW];
__device__ float g_sq[BATCH * HH];
__device__ float g_sk[BATCH * HH];
__device__ float g_wpad[64 * 176];

// ---------------- helpers ----------------
__device__ __forceinline__ void mma8(float* d, unsigned a0, unsigned a1, unsigned a2, unsigned a3,
                                     unsigned b0, unsigned b1) {
    asm volatile(
        "mma.sync.aligned.m16n8k8.row.col.f32.tf32.tf32.f32 "
        "{%0,%1,%2,%3},{%4,%5,%6,%7},{%8,%9},{%0,%1,%2,%3};\n"
        : "+f"(d[0]), "+f"(d[1]), "+f"(d[2]), "+f"(d[3])
        : "r"(a0), "r"(a1), "r"(a2), "r"(a3), "r"(b0), "r"(b1));
}
#define CPA16(dst_u32, src_ptr) \
    asm volatile("cp.async.cg.shared.global [%0], [%1], 16;" :: "r"(dst_u32), "l"(src_ptr))

// ---------------- LayerNorm over channel dim (per pixel), single-read, bf16 out -------
__global__ void ln_kernel(const float* __restrict__ x, const float* __restrict__ w,
                          const float* __restrict__ b, __nv_bfloat16* __restrict__ y)
{
    long p = (long)blockIdx.x * blockDim.x + threadIdx.x;
    if (p >= (long)BATCH * HWD) return;
    int bb  = (int)(p >> 16);
    int pix = (int)(p & (HWD - 1));
    const float* xp = x + (long)bb * CDIM * HWD + pix;
    float v[64];
    float s = 0.f, s2 = 0.f;
#pragma unroll
    for (int c = 0; c < CDIM; c++) {
        float t = xp[(long)c * HWD];
        v[c] = t; s += t; s2 += t * t;
    }
    float mu  = s * (1.0f / CDIM);
    float var = s2 * (1.0f / CDIM) - mu * mu;
    float inv = rsqrtf(var + 1e-5f);
    __nv_bfloat16* yp = y + (long)bb * CDIM * HWD + pix;
#pragma unroll
    for (int c = 0; c < CDIM; c++)
        yp[(long)c * HWD] = __float2bfloat16((v[c] - mu) * inv * w[c] + b[c]);
}

// ---------------- pad ffn_out weight 64x170 -> 64x176 (zero fill) ----------------
__global__ void padw_kernel(const float* __restrict__ w, float* __restrict__ wp)
{
    int i = blockIdx.x * 256 + threadIdx.x;
    if (i >= 64 * 176) return;
    int r = i / 176, c = i - r * 176;
    wp[i] = (c < 170) ? w[r * 170 + c] : 0.f;
}

// ---------------- depthwise 3x3, warp-per-row, shuffle halos, bf16 io ----------------
__global__ void dwconv_rows_kernel(const __nv_bfloat16* __restrict__ x,
                                   const float* __restrict__ wt,
                                   const float* __restrict__ bias,
                                   __nv_bfloat16* __restrict__ y,
                                   int OC, int normCh)
{
    long bidx = blockIdx.x;
    int hb = (int)(bidx & 31) * 8;
    long bc = bidx >> 5;
    int c = (int)(bc % OC);
    int warp = threadIdx.x >> 5, lane = threadIdx.x & 31;
    int h = hb + warp;
    const __nv_bfloat16* xp = x + (bc << 16);
    float b0 = bias[c];
    float acc[8];
#pragma unroll
    for (int j = 0; j < 8; j++) acc[j] = b0;
    const float* wc = wt + c * 9;
#pragma unroll
    for (int kh = -1; kh <= 1; kh++) {
        int hh = h + kh;
        if (hh < 0 || hh >= HH) continue;
        const uint4* rowp = reinterpret_cast<const uint4*>(xp + hh * WW);
        uint4 raw = rowp[lane];
        const __nv_bfloat16* hp = reinterpret_cast<const __nv_bfloat16*>(&raw);
        float vv[8];
#pragma unroll
        for (int j = 0; j < 8; j++) vv[j] = __bfloat162float(hp[j]);
        float vm1 = __shfl_up_sync(0xffffffffu, vv[7], 1);
        if (lane == 0) vm1 = 0.f;
        float vp8 = __shfl_down_sync(0xffffffffu, vv[0], 1);
        if (lane == 31) vp8 = 0.f;
        float vals[10] = {vm1, vv[0], vv[1], vv[2], vv[3], vv[4], vv[5], vv[6], vv[7], vp8};
        const float* wr = wc + (kh + 1) * 3;
#pragma unroll
        for (int kw = 0; kw < 3; kw++) {
            float g = wr[kw];
#pragma unroll
            for (int j = 0; j < 8; j++)
                acc[j] = fmaf(g, vals[j + kw], acc[j]);
        }
    }
    if (c < normCh) {
        float s = 0.f;
#pragma unroll
        for (int j = 0; j < 8; j++) s += acc[j] * acc[j];
#pragma unroll
        for (int o = 16; o > 0; o >>= 1) s += __shfl_xor_sync(0xffffffffu, s, o);
        float inv = 1.f / fmaxf(sqrtf(s), 1e-12f);
#pragma unroll
        for (int j = 0; j < 8; j++) acc[j] *= inv;
    }
    uint4 outr;
    __nv_bfloat16* op = reinterpret_cast<__nv_bfloat16*>(&outr);
#pragma unroll
    for (int j = 0; j < 8; j++) op[j] = __float2bfloat16(acc[j]);
    reinterpret_cast<uint4*>(y + (bc << 16) + h * WW)[lane] = outr;
}

// ---------------- fused FFN depthwise 3x3 + GELU gate, warp-per-row, bf16 io ----------
__global__ void dwconv_gate_kernel(const __nv_bfloat16* __restrict__ x,
                                   const float* __restrict__ wt,
                                   const float* __restrict__ bias,
                                   __nv_bfloat16* __restrict__ g)
{
    long bidx = blockIdx.x;
    int hb = (int)(bidx & 31) * 8;
    long bc = bidx >> 5;            // b*HID + c
    int c = (int)(bc % HID);
    int b = (int)(bc / HID);
    int warp = threadIdx.x >> 5, lane = threadIdx.x & 31;
    int h = hb + warp;
    const __nv_bfloat16* xp1 = x + ((long)b * HID2 + c) * HWD;
    const __nv_bfloat16* xp2 = xp1 + (long)HID * HWD;
    float bb1 = bias[c], bb2 = bias[c + HID];
    float acc1[8], acc2[8];
#pragma unroll
    for (int j = 0; j < 8; j++) { acc1[j] = bb1; acc2[j] = bb2; }
    const float* w1 = wt + c * 9;
    const float* w2 = wt + (c + HID) * 9;
#pragma unroll
    for (int kh = -1; kh <= 1; kh++) {
        int hh = h + kh;
        if (hh < 0 || hh >= HH) continue;
#pragma unroll
        for (int half = 0; half < 2; half++) {
            const __nv_bfloat16* xp = half ? xp2 : xp1;
            float* ac = half ? acc2 : acc1;
            const float* wr0 = (half ? w2 : w1) + (kh + 1) * 3;
            uint4 raw = reinterpret_cast<const uint4*>(xp + hh * WW)[lane];
            const __nv_bfloat16* hp = reinterpret_cast<const __nv_bfloat16*>(&raw);
            float vv[8];
#pragma unroll
            for (int j = 0; j < 8; j++) vv[j] = __bfloat162float(hp[j]);
            float vm1 = __shfl_up_sync(0xffffffffu, vv[7], 1);
            if (lane == 0) vm1 = 0.f;
            float vp8 = __shfl_down_sync(0xffffffffu, vv[0], 1);
            if (lane == 31) vp8 = 0.f;
            float vals[10] = {vm1, vv[0], vv[1], vv[2], vv[3], vv[4], vv[5], vv[6], vv[7], vp8};
#pragma unroll
            for (int kw = 0; kw < 3; kw++) {
                float gg = wr0[kw];
#pragma unroll
                for (int j = 0; j < 8; j++)
                    ac[j] = fmaf(gg, vals[j + kw], ac[j]);
            }
        }
    }
    const float kk = 0.70710678118654752f;
    uint4 outr;
    __nv_bfloat16* op = reinterpret_cast<__nv_bfloat16*>(&outr);
#pragma unroll
    for (int j = 0; j < 8; j++)
        op[j] = __float2bfloat16(0.5f * acc1[j] * (1.0f + erff(acc1[j] * kk)) * acc2[j]);
    reinterpret_cast<uint4*>(g + ((long)b * HID + c) * HWD + h * WW)[lane] = outr;
}

// ---------------- hxh inverse norm: per (b,h) over (c,w), bf16 in ----------------
__global__ void hnorm_kernel(const __nv_bfloat16* __restrict__ src, float* __restrict__ out)
{
    int b = blockIdx.y, h = blockIdx.x;
    int t = threadIdx.x;
    const __nv_bfloat16* p = src + (long)b * (3 * CDIM) * HWD + (long)h * WW + t;
    float s = 0.f;
#pragma unroll
    for (int c = 0; c < CDIM; c++) { float v = __bfloat162float(p[(long)c * HWD]); s += v * v; }
    __shared__ float red[256];
    red[t] = s; __syncthreads();
    for (int o = 128; o > 0; o >>= 1) { if (t < o) red[t] += red[t + o]; __syncthreads(); }
    if (t == 0) out[b * HH + h] = 1.f / fmaxf(sqrtf(red[0]), 1e-12f);
}

// ---------------- softmax over last dim of [B, 256, 256] (fp32) ----------------
__global__ void softmax_kernel(float* __restrict__ attn, const float* __restrict__ temp,
                               const float* __restrict__ sq, const float* __restrict__ sk)
{
    int b = blockIdx.y;
    int r = blockIdx.x;
    float* row = attn + ((long)b * WW + r) * WW;
    int t = threadIdx.x;
    float v = row[t] * temp[0];
    if (sq) v *= sq[b * WW + r] * sk[b * WW + t];
    __shared__ float red[256];
    red[t] = v; __syncthreads();
    for (int o = 128; o > 0; o >>= 1) { if (t < o) red[t] = fmaxf(red[t], red[t + o]); __syncthreads(); }
    float mx = red[0]; __syncthreads();
    float e = __expf(v - mx);
    red[t] = e; __syncthreads();
    for (int o = 128; o > 0; o >>= 1) { if (t < o) red[t] += red[t + o]; __syncthreads(); }
    row[t] = e * (1.f / red[0]);
}

// ---------------- gram kernel, bf16 operands, fp32 atomic out (unchanged) -------------
template<int L>
__global__ void __launch_bounds__(256, 2) gram_kernel(
    const __nv_bfloat16* __restrict__ Qb, const __nv_bfloat16* __restrict__ Kb,
    float* __restrict__ Cb, int KS)
{
    constexpr int P0 = 136;
    constexpr int P1 = 24;
    constexpr int SSZ = (L == 0) ? 2 * 16 * P0 : 2 * 128 * P1;
    __shared__ __align__(16) __nv_bfloat16 As[SSZ];
    __shared__ __align__(16) __nv_bfloat16 Bs[SSZ];

    int z = blockIdx.z;
    int b = z / KS, ks = z - b * KS;
    const __nv_bfloat16* Q = Qb + (long)b * (3 * CDIM * HWD);
    const __nv_bfloat16* Kp = Kb + (long)b * (3 * CDIM * HWD);
    float* C = Cb + (long)b * 65536;
    int m0 = blockIdx.x * 128, n0 = blockIdx.y * 128;
    int kchunk = 16384 / KS;
    int kbeg = ks * kchunk, kend = kbeg + kchunk;

    int tid = threadIdx.x, lane = tid & 31, warp = tid >> 5;
    int wm = warp & 1, wn = warp >> 1;
    int r = lane >> 2, c = lane & 3;

    unsigned sA = (unsigned)__cvta_generic_to_shared(As);
    unsigned sB = (unsigned)__cvta_generic_to_shared(Bs);

    auto loadStage = [&](int buf, int k0) {
        if (L == 0) {
            int row = tid >> 4;
            int q   = tid & 15;
            const __nv_bfloat16* gA = Q  + (long)(k0 + row) * 256 + m0;
            const __nv_bfloat16* gB = Kp + (long)(k0 + row) * 256 + n0;
            unsigned dA = sA + ((buf * 16 + row) * P0) * 2;
            unsigned dB = sB + ((buf * 16 + row) * P0) * 2;
            CPA16(dA + q * 16, gA + q * 8);
            CPA16(dB + q * 16, gB + q * 8);
        } else {
            int m  = tid >> 1;
            int qi = tid & 1;
            long kb = (long)(k0 >> 8) * 65536 + (k0 & 255);
            const __nv_bfloat16* gA = Q  + (long)(m0 + m) * 256 + kb;
            const __nv_bfloat16* gB = Kp + (long)(n0 + m) * 256 + kb;
            unsigned dA = sA + ((buf * 128 + m) * P1) * 2;
            unsigned dB = sB + ((buf * 128 + m) * P1) * 2;
            CPA16(dA + qi * 16, gA + qi * 8);
            CPA16(dB + qi * 16, gB + qi * 8);
        }
    };

    float acc[16][4];
#pragma unroll
    for (int i = 0; i < 16; i++)
#pragma unroll
        for (int j = 0; j < 4; j++) acc[i][j] = 0.f;

    loadStage(0, kbeg);
    asm volatile("cp.async.commit_group;");
    int buf = 0;

    for (int k0 = kbeg; k0 < kend; k0 += 16) {
        int kn = k0 + 16;
        if (kn < kend) loadStage(buf ^ 1, kn);
        asm volatile("cp.async.commit_group;");
        asm volatile("cp.async.wait_group 1;");
        __syncthreads();

        const __nv_bfloat16* A_ = As + (L == 0 ? buf * 16 * P0 : buf * 128 * P1);
        const __nv_bfloat16* B_ = Bs + (L == 0 ? buf * 16 * P0 : buf * 128 * P1);
#pragma unroll
        for (int ks2 = 0; ks2 < 2; ks2++) {
            int kc = ks2 * 8 + c;
            unsigned a0[4], a1[4], a2[4], a3[4];
#pragma unroll
            for (int mt = 0; mt < 4; mt++) {
                int mr = wm * 64 + mt * 16 + r;
                if (L == 0) {
                    a0[mt] = __float_as_uint(__bfloat162float(A_[kc * P0 + mr]));
                    a1[mt] = __float_as_uint(__bfloat162float(A_[kc * P0 + mr + 8]));
                    a2[mt] = __float_as_uint(__bfloat162float(A_[(kc + 4) * P0 + mr]));
                    a3[mt] = __float_as_uint(__bfloat162float(A_[(kc + 4) * P0 + mr + 8]));
                } else {
                    a0[mt] = __float_as_uint(__bfloat162float(A_[mr * P1 + kc]));
                    a1[mt] = __float_as_uint(__bfloat162float(A_[(mr + 8) * P1 + kc]));
                    a2[mt] = __float_as_uint(__bfloat162float(A_[mr * P1 + kc + 4]));
                    a3[mt] = __float_as_uint(__bfloat162float(A_[(mr + 8) * P1 + kc + 4]));
                }
            }
#pragma unroll
            for (int j = 0; j < 4; j++) {
                int nn = wn * 32 + j * 8 + r;
                unsigned b0, b1;
                if (L == 0) {
                    b0 = __float_as_uint(__bfloat162float(B_[kc * P0 + nn]));
                    b1 = __float_as_uint(__bfloat162float(B_[(kc + 4) * P0 + nn]));
                } else {
                    b0 = __float_as_uint(__bfloat162float(B_[nn * P1 + kc]));
                    b1 = __float_as_uint(__bfloat162float(B_[nn * P1 + kc + 4]));
                }
#pragma unroll
                for (int mt = 0; mt < 4; mt++)
                    mma8(acc[mt * 4 + j], a0[mt], a1[mt], a2[mt], a3[mt], b0, b1);
            }
        }
        __syncthreads();
        buf ^= 1;
    }

#pragma unroll
    for (int mt = 0; mt < 4; mt++) {
#pragma unroll
        for (int j = 0; j < 4; j++) {
            int mrow = m0 + wm * 64 + mt * 16 + r;
            int n    = n0 + wn * 32 + j * 8 + c * 2;
            float* ci = acc[mt * 4 + j];
            atomicAdd(&C[(long)mrow * 256 + n],           ci[0]);
            atomicAdd(&C[(long)mrow * 256 + n + 1],       ci[1]);
            atomicAdd(&C[(long)(mrow + 8) * 256 + n],     ci[2]);
            atomicAdd(&C[(long)(mrow + 8) * 256 + n + 1], ci[3]);
        }
    }
}

// ---------------- mma3: BM=128, BN=128, BK=16, 256 threads, mixed dtypes --------------
// C[m,n] = sum_k A[m*lda + k] * B[k*sbk + n]  (+bias[m])
// A rows clamped to M-1, epilogue masked. K = kit16*16.
template<int ABF, int BBF, int CBF>
__global__ void __launch_bounds__(256, 2) mma3_kernel(
    const void* __restrict__ Av, const void* __restrict__ Bv, void* __restrict__ Cv,
    int M, int kit16, int lda, long sbk, int ldc, int zdiv,
    long sA1, long sA2, long sB1, long sB2, long sC1, long sC2,
    const float* __restrict__ bias)
{
    constexpr int PA = ABF ? 24 : 20;
    constexpr int PB = BBF ? 136 : 132;
    constexpr int esA = ABF ? 2 : 4;
    constexpr int esB = BBF ? 2 : 4;
    constexpr int esC = CBF ? 2 : 4;
    constexpr int EA = ABF ? 8 : 4;
    constexpr int EB = BBF ? 8 : 4;
    constexpr int cprA = 16 / EA;            // chunks per A row
    constexpr int cprB = 128 / EB;           // chunks per B row
    __shared__ __align__(16) char AsRaw[2 * 128 * PA * esA];
    __shared__ __align__(16) char BsRaw[2 * 16 * PB * esB];

    int z = blockIdx.z;
    int z1 = z / zdiv, z2 = z - z1 * zdiv;
    const char* Apc = (const char*)Av + ((long)z1 * sA1 + (long)z2 * sA2) * esA;
    const char* Bpc = (const char*)Bv + ((long)z1 * sB1 + (long)z2 * sB2) * esB;
    char*       Cpc = (char*)Cv + ((long)z1 * sC1 + (long)z2 * sC2) * esC;

    int m0 = blockIdx.x * 128;
    int n0 = blockIdx.y * 128;

    int tid = threadIdx.x, lane = tid & 31, warp = tid >> 5;
    int wm = warp & 1, wn = warp >> 1;
    int r = lane >> 2, c = lane & 3;

    unsigned sAu = (unsigned)__cvta_generic_to_shared(AsRaw);
    unsigned sBu = (unsigned)__cvta_generic_to_shared(BsRaw);

    auto loadStage = [&](int buf, int kit) {
        int k0 = kit * 16;
#pragma unroll
        for (int i = 0; i < 128 * cprA / 256; i++) {
            int q = tid + i * 256;
            int m = q / cprA, sub = q - m * cprA;
            int gm = min(m0 + m, M - 1);
            CPA16(sAu + ((buf * 128 + m) * PA + sub * EA) * esA,
                  Apc + ((long)gm * lda + k0 + sub * EA) * esA);
        }
#pragma unroll
        for (int i = 0; i < 16 * cprB / 256; i++) {
            int q = tid + i * 256;
            int k = q / cprB, sub = q - k * cprB;
            CPA16(sBu + ((buf * 16 + k) * PB + sub * EB) * esB,
                  Bpc + ((long)(k0 + k) * sbk + n0 + sub * EB) * esB);
        }
    };

    float acc[16][4];
#pragma unroll
    for (int i = 0; i < 16; i++)
#pragma unroll
        for (int j = 0; j < 4; j++) acc[i][j] = 0.f;

    loadStage(0, 0);
    asm volatile("cp.async.commit_group;");
    int buf = 0;

    for (int kit = 0; kit < kit16; kit++) {
        if (kit + 1 < kit16) loadStage(buf ^ 1, kit + 1);
        asm volatile("cp.async.commit_group;");
        asm volatile("cp.async.wait_group 1;");
        __syncthreads();

        const char* A_ = AsRaw + buf * 128 * PA * esA;
        const char* B_ = BsRaw + buf * 16 * PB * esB;
        auto ldA = [&](int idx) -> unsigned {
            if (ABF) return __float_as_uint(__bfloat162float(((const __nv_bfloat16*)A_)[idx]));
            return __float_as_uint(((const float*)A_)[idx]);
        };
        auto ldB = [&](int idx) -> unsigned {
            if (BBF) return __float_as_uint(__bfloat162float(((const __nv_bfloat16*)B_)[idx]));
            return __float_as_uint(((const float*)B_)[idx]);
        };
#pragma unroll
        for (int ks2 = 0; ks2 < 2; ks2++) {
            int kc = ks2 * 8 + c;
            unsigned a0[4], a1[4], a2[4], a3[4];
#pragma unroll
            for (int mt = 0; mt < 4; mt++) {
                int mr = wm * 64 + mt * 16 + r;
                a0[mt] = ldA(mr * PA + kc);
                a1[mt] = ldA((mr + 8) * PA + kc);
                a2[mt] = ldA(mr * PA + kc + 4);
                a3[mt] = ldA((mr + 8) * PA + kc + 4);
            }
#pragma unroll
            for (int j = 0; j < 4; j++) {
                int nn = wn * 32 + j * 8 + r;
                unsigned b0 = ldB(kc * PB + nn);
                unsigned b1 = ldB((kc + 4) * PB + nn);
#pragma unroll
                for (int mt = 0; mt < 4; mt++)
                    mma8(acc[mt * 4 + j], a0[mt], a1[mt], a2[mt], a3[mt], b0, b1);
            }
        }
        __syncthreads();
        buf ^= 1;
    }

#pragma unroll
    for (int mt = 0; mt < 4; mt++) {
#pragma unroll
        for (int j = 0; j < 4; j++) {
            int mA = m0 + wm * 64 + mt * 16 + r;
            int n  = n0 + wn * 32 + j * 8 + c * 2;
            float* ci = acc[mt * 4 + j];
#pragma unroll
            for (int half = 0; half < 2; half++) {
                int mrow = mA + half * 8;
                if (mrow >= M) continue;
                float bv = bias ? bias[mrow] : 0.f;
                float v0 = ci[half * 2 + 0] + bv;
                float v1 = ci[half * 2 + 1] + bv;
                long off = (long)mrow * ldc + n;
                if (CBF) {
                    __nv_bfloat162 h = __floats2bfloat162_rn(v0, v1);
                    *reinterpret_cast<__nv_bfloat162*>(Cpc + off * 2) = h;
                } else {
                    *reinterpret_cast<float2*>(Cpc + off * 4) = make_float2(v0, v1);
                }
            }
        }
    }
}

// ---------------- mma2 (kept for M=64 residual GEMMs): BM=64, BN=64, 128 thr ----------
template<int MT, int ABF, int BBF, int CBF>
__global__ void __launch_bounds__(128, (MT == 1) ? 4 : 3) mma2_kernel(
    const void* __restrict__ Av, const void* __restrict__ Bv, void* __restrict__ Cv,
    int M, int kit16, int lda, long sbk, int ldc, int zdiv,
    long sA1, long sA2, long sB1, long sB2, long sC1, long sC2,
    const float* __restrict__ bias,
    const float* __restrict__ res, long sR1, long sR2)
{
    constexpr int BM = MT * 64;
    constexpr int PA = ABF ? 24 : 20;
    constexpr int PB = BBF ? 72 : 68;
    constexpr int esA = ABF ? 2 : 4;
    constexpr int esB = BBF ? 2 : 4;
    constexpr int esC = CBF ? 2 : 4;
    constexpr int EA = ABF ? 8 : 4;
    constexpr int EB = BBF ? 8 : 4;
    constexpr int cprA = 16 / EA;
    constexpr int cprB = 64 / EB;
    __shared__ __align__(16) char AsRaw[2 * BM * PA * esA];
    __shared__ __align__(16) char BsRaw[2 * 16 * PB * esB];

    int z = blockIdx.z;
    int z1 = z / zdiv, z2 = z - z1 * zdiv;
    const char* Apc = (const char*)Av + ((long)z1 * sA1 + (long)z2 * sA2) * esA;
    const char* Bpc = (const char*)Bv + ((long)z1 * sB1 + (long)z2 * sB2) * esB;
    char*       Cpc = (char*)Cv + ((long)z1 * sC1 + (long)z2 * sC2) * esC;

    int m0 = blockIdx.x * BM;
    int n0 = blockIdx.y * 64;

    int tid = threadIdx.x, lane = tid & 31, warp = tid >> 5;
    int r = lane >> 2, c = lane & 3;

    unsigned sAu = (unsigned)__cvta_generic_to_shared(AsRaw);
    unsigned sBu = (unsigned)__cvta_generic_to_shared(BsRaw);

    auto loadStage = [&](int buf, int kit) {
        int k0 = kit * 16;
#pragma unroll
        for (int i = 0; i < BM * cprA / 128; i++) {
            int q = tid + i * 128;
            int m = q / cprA, sub = q - m * cprA;
            int gm = min(m0 + m, M - 1);
            CPA16(sAu + ((buf * BM + m) * PA + sub * EA) * esA,
                  Apc + ((long)gm * lda + k0 + sub * EA) * esA);
        }
#pragma unroll
        for (int i = 0; i < 16 * cprB / 128; i++) {
            int q = tid + i * 128;
            int k = q / cprB, sub = q - k * cprB;
            CPA16(sBu + ((buf * 16 + k) * PB + sub * EB) * esB,
                  Bpc + ((long)(k0 + k) * sbk + n0 + sub * EB) * esB);
        }
    };

    float acc[MT * 8][4];
#pragma unroll
    for (int i = 0; i < MT * 8; i++)
#pragma unroll
        for (int j = 0; j < 4; j++) acc[i][j] = 0.f;

    loadStage(0, 0);
    asm volatile("cp.async.commit_group;");
    int buf = 0;

    for (int kit = 0; kit < kit16; kit++) {
        if (kit + 1 < kit16) loadStage(buf ^ 1, kit + 1);
        asm volatile("cp.async.commit_group;");
        asm volatile("cp.async.wait_group 1;");
        __syncthreads();

        const char* A_ = AsRaw + buf * BM * PA * esA;
        const char* B_ = BsRaw + buf * 16 * PB * esB;
        auto ldA = [&](int idx) -> unsigned {
            if (ABF) return __float_as_uint(__bfloat162float(((const __nv_bfloat16*)A_)[idx]));
            return __float_as_uint(((const float*)A_)[idx]);
        };
        auto ldB = [&](int idx) -> unsigned {
            if (BBF) return __float_as_uint(__bfloat162float(((const __nv_bfloat16*)B_)[idx]));
            return __float_as_uint(((const float*)B_)[idx]);
        };
#pragma unroll
        for (int ks2 = 0; ks2 < 2; ks2++) {
            int kc = ks2 * 8 + c;
            unsigned a0[MT], a1[MT], a2[MT], a3[MT];
#pragma unroll
            for (int mt = 0; mt < MT; mt++) {
                int mr = warp * (MT * 16) + mt * 16 + r;
                a0[mt] = ldA(mr * PA + kc);
                a1[mt] = ldA((mr + 8) * PA + kc);
                a2[mt] = ldA(mr * PA + kc + 4);
                a3[mt] = ldA((mr + 8) * PA + kc + 4);
            }
#pragma unroll
            for (int j = 0; j < 8; j++) {
                int nn = j * 8 + r;
                unsigned b0 = ldB(kc * PB + nn);
                unsigned b1 = ldB((kc + 4) * PB + nn);
#pragma unroll
                for (int mt = 0; mt < MT; mt++)
                    mma8(acc[mt * 8 + j], a0[mt], a1[mt], a2[mt], a3[mt], b0, b1);
            }
        }
        __syncthreads();
        buf ^= 1;
    }

    const float* Rp = res ? res + (long)z1 * sR1 + (long)z2 * sR2 : nullptr;
#pragma unroll
    for (int mt = 0; mt < MT; mt++) {
#pragma unroll
        for (int j = 0; j < 8; j++) {
            int mA = m0 + warp * (MT * 16) + mt * 16 + r;
            int n  = n0 + j * 8 + c * 2;
            float* ci = acc[mt * 8 + j];
#pragma unroll
            for (int half = 0; half < 2; half++) {
                int mrow = mA + half * 8;
                if (mrow >= M) continue;
                float bv = bias ? bias[mrow] : 0.f;
                float v0 = ci[half * 2 + 0] + bv;
                float v1 = ci[half * 2 + 1] + bv;
                long off = (long)mrow * ldc + n;
                if (Rp) { v0 += Rp[off]; v1 += Rp[off + 1]; }
                if (CBF) {
                    __nv_bfloat162 h = __floats2bfloat162_rn(v0, v1);
                    *reinterpret_cast<__nv_bfloat162*>(Cpc + off * 2) = h;
                } else {
                    *reinterpret_cast<float2*>(Cpc + off * 4) = make_float2(v0, v1);
                }
            }
        }
    }
}

extern "C" void kernel_launch(void* const* d_in, const int* in_sizes, int n_in,
                              void* d_out, int out_size)
{
    const float* x        = (const float*)d_in[0];
    const float* w_ln_w   = (const float*)d_in[2];
    const float* w_ln_b   = (const float*)d_in[3];
    const float* w_qkv_w  = (const float*)d_in[4];
    const float* w_qkv_b  = (const float*)d_in[5];
    const float* w_dw_w   = (const float*)d_in[6];
    const float* w_dw_b   = (const float*)d_in[7];
    const float* w_proj_w = (const float*)d_in[8];
    const float* w_proj_b = (const float*)d_in[9];
    const float* w_temp   = (const float*)d_in[10];
    const float* h_ln_w   = (const float*)d_in[11];
    const float* h_ln_b   = (const float*)d_in[12];
    const float* h_qkv_w  = (const float*)d_in[13];
    const float* h_qkv_b  = (const float*)d_in[14];
    const float* h_dw_w   = (const float*)d_in[15];
    const float* h_dw_b   = (const float*)d_in[16];
    const float* h_proj_w = (const float*)d_in[17];
    const float* h_proj_b = (const float*)d_in[18];
    const float* h_temp   = (const float*)d_in[19];
    const float* n2_w     = (const float*)d_in[20];
    const float* n2_b     = (const float*)d_in[21];
    const float* ffn_in_w = (const float*)d_in[22];
    const float* ffn_in_b = (const float*)d_in[23];
    const float* ffn_dw_w = (const float*)d_in[24];
    const float* ffn_dw_b = (const float*)d_in[25];
    const float* ffn_out_w= (const float*)d_in[26];
    const float* ffn_out_b= (const float*)d_in[27];
    float* out = (float*)d_out;

    __nv_bfloat16 *bufA, *qkv1, *qkv2;
    float *bufM, *bufZ, *attn, *sq, *sk, *wpad;
    cudaGetSymbolAddress((void**)&bufA, g_bufA);
    cudaGetSymbolAddress((void**)&bufM, g_bufM);
    cudaGetSymbolAddress((void**)&bufZ, g_bufZ);
    cudaGetSymbolAddress((void**)&qkv1, g_qkv1);
    cudaGetSymbolAddress((void**)&qkv2, g_qkv2);
    cudaGetSymbolAddress((void**)&attn, g_attn);
    cudaGetSymbolAddress((void**)&sq,   g_sq);
    cudaGetSymbolAddress((void**)&sk,   g_sk);
    cudaGetSymbolAddress((void**)&wpad, g_wpad);

    const long sX = (long)CDIM * HWD;
    const long sQ = (long)3 * CDIM * HWD;
    const int KS = 32;

    padw_kernel<<<(64 * 176 + 255) / 256, 256>>>(ffn_out_w, wpad);

    // ================= attention (WxW) =================
    ln_kernel<<<(BATCH * HWD) / 256, 256>>>(x, w_ln_w, w_ln_b, bufA);
    // qkv: A=W fp32 [192,64], B=ln bf16, C=qkv1 bf16, BM=128 grid(2,512,4)
    mma3_kernel<0,1,1><<<dim3(2, 512, BATCH), 256>>>(w_qkv_w, bufA, qkv1,
        192, 4, 64, HWD, HWD, 1, 0,0, sX,0, sQ,0, w_qkv_b);
    dwconv_rows_kernel<<<BATCH*192*32, 256>>>(qkv1, w_dw_w, w_dw_b, qkv2, 192, 128);
    cudaMemsetAsync(attn, 0, (size_t)BATCH * WW * WW * sizeof(float));
    gram_kernel<0><<<dim3(2, 2, BATCH * KS), 256>>>(qkv2, qkv2 + 64*(long)HWD, attn, KS);
    softmax_kernel<<<dim3(WW, BATCH), 256>>>(attn, w_temp, nullptr, nullptr);
    // AV: A=v bf16 [16384,256], B=attn fp32, C=bufA bf16, grid(128,2,4)
    mma3_kernel<1,0,1><<<dim3(128, 2, BATCH), 256>>>(qkv2 + 128*(long)HWD, attn, bufA,
        CHROWS, 16, 256, 256, 256, 1, sQ,0, (long)WW*WW,0, sX,0, nullptr);
    // proj + residual x -> bufM (fp32)
    mma2_kernel<1,0,1,0><<<dim3(1, 1024, BATCH), 128>>>(w_proj_w, bufA, bufM,
        64, 4, 64, HWD, HWD, 1, 0,0, sX,0, sX,0, w_proj_b, x, sX,0);

    // ================= attention (HxH) =================
    ln_kernel<<<(BATCH * HWD) / 256, 256>>>(bufM, h_ln_w, h_ln_b, bufA);
    mma3_kernel<0,1,1><<<dim3(2, 512, BATCH), 256>>>(h_qkv_w, bufA, qkv1,
        192, 4, 64, HWD, HWD, 1, 0,0, sX,0, sQ,0, h_qkv_b);
    dwconv_rows_kernel<<<BATCH*192*32, 256>>>(qkv1, h_dw_w, h_dw_b, qkv2, 192, 0);
    hnorm_kernel<<<dim3(HH, BATCH), 256>>>(qkv2,                sq);
    hnorm_kernel<<<dim3(HH, BATCH), 256>>>(qkv2 + 64*(long)HWD, sk);
    cudaMemsetAsync(attn, 0, (size_t)BATCH * WW * WW * sizeof(float));
    gram_kernel<1><<<dim3(2, 2, BATCH * KS), 256>>>(qkv2, qkv2 + 64*(long)HWD, attn, KS);
    softmax_kernel<<<dim3(WW, BATCH), 256>>>(attn, h_temp, sq, sk);
    // AV: per (b,c): A=attn fp32 [256,256], B=v bf16, C=bufA bf16, grid(2,2,BATCH*64)
    mma3_kernel<0,1,1><<<dim3(2, 2, BATCH * 64), 256>>>(attn, qkv2 + 128*(long)HWD, bufA,
        256, 16, 256, 256, 256, 64, (long)WW*WW,0, sQ,(long)HWD, sX,(long)HWD, nullptr);
    // proj + residual m -> bufZ (fp32)
    mma2_kernel<1,0,1,0><<<dim3(1, 1024, BATCH), 128>>>(h_proj_w, bufA, bufZ,
        64, 4, 64, HWD, HWD, 1, 0,0, sX,0, sX,0, h_proj_b, bufM, sX,0);

    // ================= FFN =================
    ln_kernel<<<(BATCH * HWD) / 256, 256>>>(bufZ, n2_w, n2_b, bufA);
    // ffn_in: A=W fp32 [340,64], B=ln bf16, C=qkv1 bf16, grid(3,512,4)
    mma3_kernel<0,1,1><<<dim3(3, 512, BATCH), 256>>>(ffn_in_w, bufA, qkv1,
        HID2, 4, 64, HWD, HWD, 1, 0,0, sX,0, (long)HID2*HWD,0, ffn_in_b);
    dwconv_gate_kernel<<<BATCH*HID*32, 256>>>(qkv1, ffn_dw_w, ffn_dw_b, qkv2);
    // out = Wout(padded) @ gated(bf16) + bias + z (fp32 out)
    mma2_kernel<1,0,1,0><<<dim3(1, 1024, BATCH), 128>>>(wpad, qkv2, out,
        64, 11, 176, HWD, HWD, 1, 0,0, (long)HID*HWD,0, sX,0, ffn_out_b, bufZ, sX,0);
}

// round 16
// speedup vs baseline: 1.1387x; 1.1387x over previous
#include <cuda_runtime.h>
#include <cuda_bf16.h>
#include <math.h>

#define BATCH 4
#define CDIM  64
#define HH    256
#define WW    256
#define HWD   65536          // H*W
#define CHROWS 16384         // C*H
#define HID   170
#define HID2  340

// ---------------- scratch (device globals; no allocations allowed) ----------------
__device__ __nv_bfloat16 g_bufA[(size_t)BATCH * CDIM * HWD];   // ln out / AV out (bf16)
__device__ float         g_bufM[(size_t)BATCH * CDIM * HWD];   // wxw output (fp32)
__device__ float         g_bufZ[(size_t)BATCH * CDIM * HWD];   // hxh output (fp32)
__device__ __nv_bfloat16 g_qkv1[(size_t)BATCH * HID2 * HWD];   // pre-dwconv qkv / ffn hidden
__device__ __nv_bfloat16 g_qkv2[(size_t)BATCH * HID2 * HWD];   // post-dwconv qkv / gated
__device__ float         g_attn[(size_t)BATCH * WW * WW];
__device__ float g_sq[BATCH * HH];
__device__ float g_sk[BATCH * HH];
__device__ float g_wpad[64 * 176];

// ---------------- helpers ----------------
__device__ __forceinline__ void mma8(float* d, unsigned a0, unsigned a1, unsigned a2, unsigned a3,
                                     unsigned b0, unsigned b1) {
    asm volatile(
        "mma.sync.aligned.m16n8k8.row.col.f32.tf32.tf32.f32 "
        "{%0,%1,%2,%3},{%4,%5,%6,%7},{%8,%9},{%0,%1,%2,%3};\n"
        : "+f"(d[0]), "+f"(d[1]), "+f"(d[2]), "+f"(d[3])
        : "r"(a0), "r"(a1), "r"(a2), "r"(a3), "r"(b0), "r"(b1));
}
#define CPA16(dst_u32, src_ptr) \
    asm volatile("cp.async.cg.shared.global [%0], [%1], 16;" :: "r"(dst_u32), "l"(src_ptr))

// ---------------- LayerNorm over channel dim (per pixel), single-read, bf16 out -------
__global__ void ln_kernel(const float* __restrict__ x, const float* __restrict__ w,
                          const float* __restrict__ b, __nv_bfloat16* __restrict__ y)
{
    long p = (long)blockIdx.x * blockDim.x + threadIdx.x;
    if (p >= (long)BATCH * HWD) return;
    int bb  = (int)(p >> 16);
    int pix = (int)(p & (HWD - 1));
    const float* xp = x + (long)bb * CDIM * HWD + pix;
    float v[64];
    float s = 0.f, s2 = 0.f;
#pragma unroll
    for (int c = 0; c < CDIM; c++) {
        float t = xp[(long)c * HWD];
        v[c] = t; s += t; s2 += t * t;
    }
    float mu  = s * (1.0f / CDIM);
    float var = s2 * (1.0f / CDIM) - mu * mu;
    float inv = rsqrtf(var + 1e-5f);
    __nv_bfloat16* yp = y + (long)bb * CDIM * HWD + pix;
#pragma unroll
    for (int c = 0; c < CDIM; c++)
        yp[(long)c * HWD] = __float2bfloat16((v[c] - mu) * inv * w[c] + b[c]);
}

// ---------------- pad ffn_out weight 64x170 -> 64x176 (zero fill) ----------------
__global__ void padw_kernel(const float* __restrict__ w, float* __restrict__ wp)
{
    int i = blockIdx.x * 256 + threadIdx.x;
    if (i >= 64 * 176) return;
    int r = i / 176, c = i - r * 176;
    wp[i] = (c < 170) ? w[r * 170 + c] : 0.f;
}

// ---------------- depthwise 3x3, warp-per-row, shuffle halos, bf16 io ----------------
__global__ void dwconv_rows_kernel(const __nv_bfloat16* __restrict__ x,
                                   const float* __restrict__ wt,
                                   const float* __restrict__ bias,
                                   __nv_bfloat16* __restrict__ y,
                                   int OC, int normCh)
{
    long bidx = blockIdx.x;
    int hb = (int)(bidx & 31) * 8;
    long bc = bidx >> 5;
    int c = (int)(bc % OC);
    int warp = threadIdx.x >> 5, lane = threadIdx.x & 31;
    int h = hb + warp;
    const __nv_bfloat16* xp = x + (bc << 16);
    float b0 = bias[c];
    float acc[8];
#pragma unroll
    for (int j = 0; j < 8; j++) acc[j] = b0;
    const float* wc = wt + c * 9;
#pragma unroll
    for (int kh = -1; kh <= 1; kh++) {
        int hh = h + kh;
        if (hh < 0 || hh >= HH) continue;
        const uint4* rowp = reinterpret_cast<const uint4*>(xp + hh * WW);
        uint4 raw = rowp[lane];
        const __nv_bfloat16* hp = reinterpret_cast<const __nv_bfloat16*>(&raw);
        float vv[8];
#pragma unroll
        for (int j = 0; j < 8; j++) vv[j] = __bfloat162float(hp[j]);
        float vm1 = __shfl_up_sync(0xffffffffu, vv[7], 1);
        if (lane == 0) vm1 = 0.f;
        float vp8 = __shfl_down_sync(0xffffffffu, vv[0], 1);
        if (lane == 31) vp8 = 0.f;
        float vals[10] = {vm1, vv[0], vv[1], vv[2], vv[3], vv[4], vv[5], vv[6], vv[7], vp8};
        const float* wr = wc + (kh + 1) * 3;
#pragma unroll
        for (int kw = 0; kw < 3; kw++) {
            float g = wr[kw];
#pragma unroll
            for (int j = 0; j < 8; j++)
                acc[j] = fmaf(g, vals[j + kw], acc[j]);
        }
    }
    if (c < normCh) {
        float s = 0.f;
#pragma unroll
        for (int j = 0; j < 8; j++) s += acc[j] * acc[j];
#pragma unroll
        for (int o = 16; o > 0; o >>= 1) s += __shfl_xor_sync(0xffffffffu, s, o);
        float inv = 1.f / fmaxf(sqrtf(s), 1e-12f);
#pragma unroll
        for (int j = 0; j < 8; j++) acc[j] *= inv;
    }
    uint4 outr;
    __nv_bfloat16* op = reinterpret_cast<__nv_bfloat16*>(&outr);
#pragma unroll
    for (int j = 0; j < 8; j++) op[j] = __float2bfloat16(acc[j]);
    reinterpret_cast<uint4*>(y + (bc << 16) + h * WW)[lane] = outr;
}

// ---------------- fused FFN depthwise 3x3 + GELU gate, warp-per-row, bf16 io ----------
__global__ void dwconv_gate_kernel(const __nv_bfloat16* __restrict__ x,
                                   const float* __restrict__ wt,
                                   const float* __restrict__ bias,
                                   __nv_bfloat16* __restrict__ g)
{
    long bidx = blockIdx.x;
    int hb = (int)(bidx & 31) * 8;
    long bc = bidx >> 5;            // b*HID + c
    int c = (int)(bc % HID);
    int b = (int)(bc / HID);
    int warp = threadIdx.x >> 5, lane = threadIdx.x & 31;
    int h = hb + warp;
    const __nv_bfloat16* xp1 = x + ((long)b * HID2 + c) * HWD;
    const __nv_bfloat16* xp2 = xp1 + (long)HID * HWD;
    float bb1 = bias[c], bb2 = bias[c + HID];
    float acc1[8], acc2[8];
#pragma unroll
    for (int j = 0; j < 8; j++) { acc1[j] = bb1; acc2[j] = bb2; }
    const float* w1 = wt + c * 9;
    const float* w2 = wt + (c + HID) * 9;
#pragma unroll
    for (int kh = -1; kh <= 1; kh++) {
        int hh = h + kh;
        if (hh < 0 || hh >= HH) continue;
#pragma unroll
        for (int half = 0; half < 2; half++) {
            const __nv_bfloat16* xp = half ? xp2 : xp1;
            float* ac = half ? acc2 : acc1;
            const float* wr0 = (half ? w2 : w1) + (kh + 1) * 3;
            uint4 raw = reinterpret_cast<const uint4*>(xp + hh * WW)[lane];
            const __nv_bfloat16* hp = reinterpret_cast<const __nv_bfloat16*>(&raw);
            float vv[8];
#pragma unroll
            for (int j = 0; j < 8; j++) vv[j] = __bfloat162float(hp[j]);
            float vm1 = __shfl_up_sync(0xffffffffu, vv[7], 1);
            if (lane == 0) vm1 = 0.f;
            float vp8 = __shfl_down_sync(0xffffffffu, vv[0], 1);
            if (lane == 31) vp8 = 0.f;
            float vals[10] = {vm1, vv[0], vv[1], vv[2], vv[3], vv[4], vv[5], vv[6], vv[7], vp8};
#pragma unroll
            for (int kw = 0; kw < 3; kw++) {
                float gg = wr0[kw];
#pragma unroll
                for (int j = 0; j < 8; j++)
                    ac[j] = fmaf(gg, vals[j + kw], ac[j]);
            }
        }
    }
    const float kk = 0.70710678118654752f;
    uint4 outr;
    __nv_bfloat16* op = reinterpret_cast<__nv_bfloat16*>(&outr);
#pragma unroll
    for (int j = 0; j < 8; j++)
        op[j] = __float2bfloat16(0.5f * acc1[j] * (1.0f + erff(acc1[j] * kk)) * acc2[j]);
    reinterpret_cast<uint4*>(g + ((long)b * HID + c) * HWD + h * WW)[lane] = outr;
}

// ---------------- hxh inverse norm: per (b,h) over (c,w), bf16 in ----------------
__global__ void hnorm_kernel(const __nv_bfloat16* __restrict__ src, float* __restrict__ out)
{
    int b = blockIdx.y, h = blockIdx.x;
    int t = threadIdx.x;
    const __nv_bfloat16* p = src + (long)b * (3 * CDIM) * HWD + (long)h * WW + t;
    float s = 0.f;
#pragma unroll
    for (int c = 0; c < CDIM; c++) { float v = __bfloat162float(p[(long)c * HWD]); s += v * v; }
    __shared__ float red[256];
    red[t] = s; __syncthreads();
    for (int o = 128; o > 0; o >>= 1) { if (t < o) red[t] += red[t + o]; __syncthreads(); }
    if (t == 0) out[b * HH + h] = 1.f / fmaxf(sqrtf(red[0]), 1e-12f);
}

// ---------------- softmax over last dim of [B, 256, 256] (fp32) ----------------
__global__ void softmax_kernel(float* __restrict__ attn, const float* __restrict__ temp,
                               const float* __restrict__ sq, const float* __restrict__ sk)
{
    int b = blockIdx.y;
    int r = blockIdx.x;
    float* row = attn + ((long)b * WW + r) * WW;
    int t = threadIdx.x;
    float v = row[t] * temp[0];
    if (sq) v *= sq[b * WW + r] * sk[b * WW + t];
    __shared__ float red[256];
    red[t] = v; __syncthreads();
    for (int o = 128; o > 0; o >>= 1) { if (t < o) red[t] = fmaxf(red[t], red[t + o]); __syncthreads(); }
    float mx = red[0]; __syncthreads();
    float e = __expf(v - mx);
    red[t] = e; __syncthreads();
    for (int o = 128; o > 0; o >>= 1) { if (t < o) red[t] += red[t + o]; __syncthreads(); }
    row[t] = e * (1.f / red[0]);
}

// ---------------- gram kernel, bf16 operands, fp32 atomic out (unchanged) -------------
template<int L>
__global__ void __launch_bounds__(256, 2) gram_kernel(
    const __nv_bfloat16* __restrict__ Qb, const __nv_bfloat16* __restrict__ Kb,
    float* __restrict__ Cb, int KS)
{
    constexpr int P0 = 136;
    constexpr int P1 = 24;
    constexpr int SSZ = (L == 0) ? 2 * 16 * P0 : 2 * 128 * P1;
    __shared__ __align__(16) __nv_bfloat16 As[SSZ];
    __shared__ __align__(16) __nv_bfloat16 Bs[SSZ];

    int z = blockIdx.z;
    int b = z / KS, ks = z - b * KS;
    const __nv_bfloat16* Q = Qb + (long)b * (3 * CDIM * HWD);
    const __nv_bfloat16* Kp = Kb + (long)b * (3 * CDIM * HWD);
    float* C = Cb + (long)b * 65536;
    int m0 = blockIdx.x * 128, n0 = blockIdx.y * 128;
    int kchunk = 16384 / KS;
    int kbeg = ks * kchunk, kend = kbeg + kchunk;

    int tid = threadIdx.x, lane = tid & 31, warp = tid >> 5;
    int wm = warp & 1, wn = warp >> 1;
    int r = lane >> 2, c = lane & 3;

    unsigned sA = (unsigned)__cvta_generic_to_shared(As);
    unsigned sB = (unsigned)__cvta_generic_to_shared(Bs);

    auto loadStage = [&](int buf, int k0) {
        if (L == 0) {
            int row = tid >> 4;
            int q   = tid & 15;
            const __nv_bfloat16* gA = Q  + (long)(k0 + row) * 256 + m0;
            const __nv_bfloat16* gB = Kp + (long)(k0 + row) * 256 + n0;
            unsigned dA = sA + ((buf * 16 + row) * P0) * 2;
            unsigned dB = sB + ((buf * 16 + row) * P0) * 2;
            CPA16(dA + q * 16, gA + q * 8);
            CPA16(dB + q * 16, gB + q * 8);
        } else {
            int m  = tid >> 1;
            int qi = tid & 1;
            long kb = (long)(k0 >> 8) * 65536 + (k0 & 255);
            const __nv_bfloat16* gA = Q  + (long)(m0 + m) * 256 + kb;
            const __nv_bfloat16* gB = Kp + (long)(n0 + m) * 256 + kb;
            unsigned dA = sA + ((buf * 128 + m) * P1) * 2;
            unsigned dB = sB + ((buf * 128 + m) * P1) * 2;
            CPA16(dA + qi * 16, gA + qi * 8);
            CPA16(dB + qi * 16, gB + qi * 8);
        }
    };

    float acc[16][4];
#pragma unroll
    for (int i = 0; i < 16; i++)
#pragma unroll
        for (int j = 0; j < 4; j++) acc[i][j] = 0.f;

    loadStage(0, kbeg);
    asm volatile("cp.async.commit_group;");
    int buf = 0;

    for (int k0 = kbeg; k0 < kend; k0 += 16) {
        int kn = k0 + 16;
        if (kn < kend) loadStage(buf ^ 1, kn);
        asm volatile("cp.async.commit_group;");
        asm volatile("cp.async.wait_group 1;");
        __syncthreads();

        const __nv_bfloat16* A_ = As + (L == 0 ? buf * 16 * P0 : buf * 128 * P1);
        const __nv_bfloat16* B_ = Bs + (L == 0 ? buf * 16 * P0 : buf * 128 * P1);
#pragma unroll
        for (int ks2 = 0; ks2 < 2; ks2++) {
            int kc = ks2 * 8 + c;
            unsigned a0[4], a1[4], a2[4], a3[4];
#pragma unroll
            for (int mt = 0; mt < 4; mt++) {
                int mr = wm * 64 + mt * 16 + r;
                if (L == 0) {
                    a0[mt] = __float_as_uint(__bfloat162float(A_[kc * P0 + mr]));
                    a1[mt] = __float_as_uint(__bfloat162float(A_[kc * P0 + mr + 8]));
                    a2[mt] = __float_as_uint(__bfloat162float(A_[(kc + 4) * P0 + mr]));
                    a3[mt] = __float_as_uint(__bfloat162float(A_[(kc + 4) * P0 + mr + 8]));
                } else {
                    a0[mt] = __float_as_uint(__bfloat162float(A_[mr * P1 + kc]));
                    a1[mt] = __float_as_uint(__bfloat162float(A_[(mr + 8) * P1 + kc]));
                    a2[mt] = __float_as_uint(__bfloat162float(A_[mr * P1 + kc + 4]));
                    a3[mt] = __float_as_uint(__bfloat162float(A_[(mr + 8) * P1 + kc + 4]));
                }
            }
#pragma unroll
            for (int j = 0; j < 4; j++) {
                int nn = wn * 32 + j * 8 + r;
                unsigned b0, b1;
                if (L == 0) {
                    b0 = __float_as_uint(__bfloat162float(B_[kc * P0 + nn]));
                    b1 = __float_as_uint(__bfloat162float(B_[(kc + 4) * P0 + nn]));
                } else {
                    b0 = __float_as_uint(__bfloat162float(B_[nn * P1 + kc]));
                    b1 = __float_as_uint(__bfloat162float(B_[nn * P1 + kc + 4]));
                }
#pragma unroll
                for (int mt = 0; mt < 4; mt++)
                    mma8(acc[mt * 4 + j], a0[mt], a1[mt], a2[mt], a3[mt], b0, b1);
            }
        }
        __syncthreads();
        buf ^= 1;
    }

#pragma unroll
    for (int mt = 0; mt < 4; mt++) {
#pragma unroll
        for (int j = 0; j < 4; j++) {
            int mrow = m0 + wm * 64 + mt * 16 + r;
            int n    = n0 + wn * 32 + j * 8 + c * 2;
            float* ci = acc[mt * 4 + j];
            atomicAdd(&C[(long)mrow * 256 + n],           ci[0]);
            atomicAdd(&C[(long)mrow * 256 + n + 1],       ci[1]);
            atomicAdd(&C[(long)(mrow + 8) * 256 + n],     ci[2]);
            atomicAdd(&C[(long)(mrow + 8) * 256 + n + 1], ci[3]);
        }
    }
}

// ---------------- mma3t: 128x128x16, 256 thr, geometry as template constants ----------
// C[m,n] = sum_k A[m*LDA + k] * B[k*SBK + n]  (+bias[m]); K = kit16*16.
// All loop-carried strides compile-time (gram register recipe). Batch offsets runtime.
template<int ABF, int BBF, int CBF, int LDA, int SBK, int LDC, int ZDIV>
__global__ void __launch_bounds__(256, 2) mma3t_kernel(
    const void* __restrict__ Av, const void* __restrict__ Bv, void* __restrict__ Cv,
    int M, int kit16,
    long sA1, long sA2, long sB1, long sB2, long sC1, long sC2,
    const float* __restrict__ bias)
{
    constexpr int PA = ABF ? 24 : 20;
    constexpr int PB = BBF ? 136 : 132;
    constexpr int esA = ABF ? 2 : 4;
    constexpr int esB = BBF ? 2 : 4;
    constexpr int esC = CBF ? 2 : 4;
    constexpr int EA = ABF ? 8 : 4;
    constexpr int EB = BBF ? 8 : 4;
    constexpr int cprA = 16 / EA;
    constexpr int cprB = 128 / EB;
    __shared__ __align__(16) char AsRaw[2 * 128 * PA * esA];
    __shared__ __align__(16) char BsRaw[2 * 16 * PB * esB];

    int z = blockIdx.z;
    int z1 = z / ZDIV, z2 = z - z1 * ZDIV;
    const char* Apc = (const char*)Av + ((long)z1 * sA1 + (long)z2 * sA2) * esA;
    const char* Bpc = (const char*)Bv + ((long)z1 * sB1 + (long)z2 * sB2) * esB;
    char*       Cpc = (char*)Cv + ((long)z1 * sC1 + (long)z2 * sC2) * esC;

    int m0 = blockIdx.x * 128;
    int n0 = blockIdx.y * 128;

    int tid = threadIdx.x, lane = tid & 31, warp = tid >> 5;
    int wm = warp & 1, wn = warp >> 1;
    int r = lane >> 2, c = lane & 3;

    unsigned sAu = (unsigned)__cvta_generic_to_shared(AsRaw);
    unsigned sBu = (unsigned)__cvta_generic_to_shared(BsRaw);

    auto loadStage = [&](int buf, int kit) {
        int k0 = kit * 16;
#pragma unroll
        for (int i = 0; i < 128 * cprA / 256; i++) {
            int q = tid + i * 256;
            int m = q / cprA, sub = q - m * cprA;
            int gm = min(m0 + m, M - 1);
            CPA16(sAu + ((buf * 128 + m) * PA + sub * EA) * esA,
                  Apc + ((long)gm * LDA + k0 + sub * EA) * esA);
        }
#pragma unroll
        for (int i = 0; i < 16 * cprB / 256; i++) {
            int q = tid + i * 256;
            int k = q / cprB, sub = q - k * cprB;
            CPA16(sBu + ((buf * 16 + k) * PB + sub * EB) * esB,
                  Bpc + ((long)(k0 + k) * SBK + n0 + sub * EB) * esB);
        }
    };

    float acc[16][4];
#pragma unroll
    for (int i = 0; i < 16; i++)
#pragma unroll
        for (int j = 0; j < 4; j++) acc[i][j] = 0.f;

    loadStage(0, 0);
    asm volatile("cp.async.commit_group;");
    int buf = 0;

    for (int kit = 0; kit < kit16; kit++) {
        if (kit + 1 < kit16) loadStage(buf ^ 1, kit + 1);
        asm volatile("cp.async.commit_group;");
        asm volatile("cp.async.wait_group 1;");
        __syncthreads();

        const char* A_ = AsRaw + buf * 128 * PA * esA;
        const char* B_ = BsRaw + buf * 16 * PB * esB;
        auto ldA = [&](int idx) -> unsigned {
            if (ABF) return __float_as_uint(__bfloat162float(((const __nv_bfloat16*)A_)[idx]));
            return __float_as_uint(((const float*)A_)[idx]);
        };
        auto ldB = [&](int idx) -> unsigned {
            if (BBF) return __float_as_uint(__bfloat162float(((const __nv_bfloat16*)B_)[idx]));
            return __float_as_uint(((const float*)B_)[idx]);
        };
#pragma unroll
        for (int ks2 = 0; ks2 < 2; ks2++) {
            int kc = ks2 * 8 + c;
            unsigned a0[4], a1[4], a2[4], a3[4];
#pragma unroll
            for (int mt = 0; mt < 4; mt++) {
                int mr = wm * 64 + mt * 16 + r;
                a0[mt] = ldA(mr * PA + kc);
                a1[mt] = ldA((mr + 8) * PA + kc);
                a2[mt] = ldA(mr * PA + kc + 4);
                a3[mt] = ldA((mr + 8) * PA + kc + 4);
            }
#pragma unroll
            for (int j = 0; j < 4; j++) {
                int nn = wn * 32 + j * 8 + r;
                unsigned b0 = ldB(kc * PB + nn);
                unsigned b1 = ldB((kc + 4) * PB + nn);
#pragma unroll
                for (int mt = 0; mt < 4; mt++)
                    mma8(acc[mt * 4 + j], a0[mt], a1[mt], a2[mt], a3[mt], b0, b1);
            }
        }
        __syncthreads();
        buf ^= 1;
    }

#pragma unroll
    for (int mt = 0; mt < 4; mt++) {
#pragma unroll
        for (int j = 0; j < 4; j++) {
            int mA = m0 + wm * 64 + mt * 16 + r;
            int n  = n0 + wn * 32 + j * 8 + c * 2;
            float* ci = acc[mt * 4 + j];
#pragma unroll
            for (int half = 0; half < 2; half++) {
                int mrow = mA + half * 8;
                if (mrow >= M) continue;
                float bv = bias ? bias[mrow] : 0.f;
                float v0 = ci[half * 2 + 0] + bv;
                float v1 = ci[half * 2 + 1] + bv;
                long off = (long)mrow * LDC + n;
                if (CBF) {
                    __nv_bfloat162 h = __floats2bfloat162_rn(v0, v1);
                    *reinterpret_cast<__nv_bfloat162*>(Cpc + off * 2) = h;
                } else {
                    *reinterpret_cast<float2*>(Cpc + off * 4) = make_float2(v0, v1);
                }
            }
        }
    }
}

// ---------------- mma2 (R10-proven): BM=MT*64, BN=64, 128 thr, mixed dtypes -----------
template<int MT, int ABF, int BBF, int CBF>
__global__ void __launch_bounds__(128, (MT == 1) ? 4 : 3) mma2_kernel(
    const void* __restrict__ Av, const void* __restrict__ Bv, void* __restrict__ Cv,
    int M, int kit16, int lda, long sbk, int ldc, int zdiv,
    long sA1, long sA2, long sB1, long sB2, long sC1, long sC2,
    const float* __restrict__ bias,
    const float* __restrict__ res, long sR1, long sR2)
{
    constexpr int BM = MT * 64;
    constexpr int PA = ABF ? 24 : 20;
    constexpr int PB = BBF ? 72 : 68;
    constexpr int esA = ABF ? 2 : 4;
    constexpr int esB = BBF ? 2 : 4;
    constexpr int esC = CBF ? 2 : 4;
    constexpr int EA = ABF ? 8 : 4;
    constexpr int EB = BBF ? 8 : 4;
    constexpr int cprA = 16 / EA;
    constexpr int cprB = 64 / EB;
    __shared__ __align__(16) char AsRaw[2 * BM * PA * esA];
    __shared__ __align__(16) char BsRaw[2 * 16 * PB * esB];

    int z = blockIdx.z;
    int z1 = z / zdiv, z2 = z - z1 * zdiv;
    const char* Apc = (const char*)Av + ((long)z1 * sA1 + (long)z2 * sA2) * esA;
    const char* Bpc = (const char*)Bv + ((long)z1 * sB1 + (long)z2 * sB2) * esB;
    char*       Cpc = (char*)Cv + ((long)z1 * sC1 + (long)z2 * sC2) * esC;

    int m0 = blockIdx.x * BM;
    int n0 = blockIdx.y * 64;

    int tid = threadIdx.x, lane = tid & 31, warp = tid >> 5;
    int r = lane >> 2, c = lane & 3;

    unsigned sAu = (unsigned)__cvta_generic_to_shared(AsRaw);
    unsigned sBu = (unsigned)__cvta_generic_to_shared(BsRaw);

    auto loadStage = [&](int buf, int kit) {
        int k0 = kit * 16;
#pragma unroll
        for (int i = 0; i < BM * cprA / 128; i++) {
            int q = tid + i * 128;
            int m = q / cprA, sub = q - m * cprA;
            int gm = min(m0 + m, M - 1);
            CPA16(sAu + ((buf * BM + m) * PA + sub * EA) * esA,
                  Apc + ((long)gm * lda + k0 + sub * EA) * esA);
        }
#pragma unroll
        for (int i = 0; i < 16 * cprB / 128; i++) {
            int q = tid + i * 128;
            int k = q / cprB, sub = q - k * cprB;
            CPA16(sBu + ((buf * 16 + k) * PB + sub * EB) * esB,
                  Bpc + ((long)(k0 + k) * sbk + n0 + sub * EB) * esB);
        }
    };

    float acc[MT * 8][4];
#pragma unroll
    for (int i = 0; i < MT * 8; i++)
#pragma unroll
        for (int j = 0; j < 4; j++) acc[i][j] = 0.f;

    loadStage(0, 0);
    asm volatile("cp.async.commit_group;");
    int buf = 0;

    for (int kit = 0; kit < kit16; kit++) {
        if (kit + 1 < kit16) loadStage(buf ^ 1, kit + 1);
        asm volatile("cp.async.commit_group;");
        asm volatile("cp.async.wait_group 1;");
        __syncthreads();

        const char* A_ = AsRaw + buf * BM * PA * esA;
        const char* B_ = BsRaw + buf * 16 * PB * esB;
        auto ldA = [&](int idx) -> unsigned {
            if (ABF) return __float_as_uint(__bfloat162float(((const __nv_bfloat16*)A_)[idx]));
            return __float_as_uint(((const float*)A_)[idx]);
        };
        auto ldB = [&](int idx) -> unsigned {
            if (BBF) return __float_as_uint(__bfloat162float(((const __nv_bfloat16*)B_)[idx]));
            return __float_as_uint(((const float*)B_)[idx]);
        };
#pragma unroll
        for (int ks2 = 0; ks2 < 2; ks2++) {
            int kc = ks2 * 8 + c;
            unsigned a0[MT], a1[MT], a2[MT], a3[MT];
#pragma unroll
            for (int mt = 0; mt < MT; mt++) {
                int mr = warp * (MT * 16) + mt * 16 + r;
                a0[mt] = ldA(mr * PA + kc);
                a1[mt] = ldA((mr + 8) * PA + kc);
                a2[mt] = ldA(mr * PA + kc + 4);
                a3[mt] = ldA((mr + 8) * PA + kc + 4);
            }
#pragma unroll
            for (int j = 0; j < 8; j++) {
                int nn = j * 8 + r;
                unsigned b0 = ldB(kc * PB + nn);
                unsigned b1 = ldB((kc + 4) * PB + nn);
#pragma unroll
                for (int mt = 0; mt < MT; mt++)
                    mma8(acc[mt * 8 + j], a0[mt], a1[mt], a2[mt], a3[mt], b0, b1);
            }
        }
        __syncthreads();
        buf ^= 1;
    }

    const float* Rp = res ? res + (long)z1 * sR1 + (long)z2 * sR2 : nullptr;
#pragma unroll
    for (int mt = 0; mt < MT; mt++) {
#pragma unroll
        for (int j = 0; j < 8; j++) {
            int mA = m0 + warp * (MT * 16) + mt * 16 + r;
            int n  = n0 + j * 8 + c * 2;
            float* ci = acc[mt * 8 + j];
#pragma unroll
            for (int half = 0; half < 2; half++) {
                int mrow = mA + half * 8;
                if (mrow >= M) continue;
                float bv = bias ? bias[mrow] : 0.f;
                float v0 = ci[half * 2 + 0] + bv;
                float v1 = ci[half * 2 + 1] + bv;
                long off = (long)mrow * ldc + n;
                if (Rp) { v0 += Rp[off]; v1 += Rp[off + 1]; }
                if (CBF) {
                    __nv_bfloat162 h = __floats2bfloat162_rn(v0, v1);
                    *reinterpret_cast<__nv_bfloat162*>(Cpc + off * 2) = h;
                } else {
                    *reinterpret_cast<float2*>(Cpc + off * 4) = make_float2(v0, v1);
                }
            }
        }
    }
}

extern "C" void kernel_launch(void* const* d_in, const int* in_sizes, int n_in,
                              void* d_out, int out_size)
{
    const float* x        = (const float*)d_in[0];
    const float* w_ln_w   = (const float*)d_in[2];
    const float* w_ln_b   = (const float*)d_in[3];
    const float* w_qkv_w  = (const float*)d_in[4];
    const float* w_qkv_b  = (const float*)d_in[5];
    const float* w_dw_w   = (const float*)d_in[6];
    const float* w_dw_b   = (const float*)d_in[7];
    const float* w_proj_w = (const float*)d_in[8];
    const float* w_proj_b = (const float*)d_in[9];
    const float* w_temp   = (const float*)d_in[10];
    const float* h_ln_w   = (const float*)d_in[11];
    const float* h_ln_b   = (const float*)d_in[12];
    const float* h_qkv_w  = (const float*)d_in[13];
    const float* h_qkv_b  = (const float*)d_in[14];
    const float* h_dw_w   = (const float*)d_in[15];
    const float* h_dw_b   = (const float*)d_in[16];
    const float* h_proj_w = (const float*)d_in[17];
    const float* h_proj_b = (const float*)d_in[18];
    const float* h_temp   = (const float*)d_in[19];
    const float* n2_w     = (const float*)d_in[20];
    const float* n2_b     = (const float*)d_in[21];
    const float* ffn_in_w = (const float*)d_in[22];
    const float* ffn_in_b = (const float*)d_in[23];
    const float* ffn_dw_w = (const float*)d_in[24];
    const float* ffn_dw_b = (const float*)d_in[25];
    const float* ffn_out_w= (const float*)d_in[26];
    const float* ffn_out_b= (const float*)d_in[27];
    float* out = (float*)d_out;

    __nv_bfloat16 *bufA, *qkv1, *qkv2;
    float *bufM, *bufZ, *attn, *sq, *sk, *wpad;
    cudaGetSymbolAddress((void**)&bufA, g_bufA);
    cudaGetSymbolAddress((void**)&bufM, g_bufM);
    cudaGetSymbolAddress((void**)&bufZ, g_bufZ);
    cudaGetSymbolAddress((void**)&qkv1, g_qkv1);
    cudaGetSymbolAddress((void**)&qkv2, g_qkv2);
    cudaGetSymbolAddress((void**)&attn, g_attn);
    cudaGetSymbolAddress((void**)&sq,   g_sq);
    cudaGetSymbolAddress((void**)&sk,   g_sk);
    cudaGetSymbolAddress((void**)&wpad, g_wpad);

    const long sX = (long)CDIM * HWD;
    const long sQ = (long)3 * CDIM * HWD;
    const long sAT = (long)WW * WW;
    const int KS = 32;

    padw_kernel<<<(64 * 176 + 255) / 256, 256>>>(ffn_out_w, wpad);

    // ================= attention (WxW) =================
    ln_kernel<<<(BATCH * HWD) / 256, 256>>>(x, w_ln_w, w_ln_b, bufA);
    // qkv (R10 config): A=W fp32 [192,64], B=ln bf16, C=qkv1 bf16
    mma2_kernel<1,0,1,1><<<dim3(3, 1024, BATCH), 128>>>(w_qkv_w, bufA, qkv1,
        192, 4, 64, HWD, HWD, 1, 0,0, sX,0, sQ,0, w_qkv_b, nullptr, 0,0);
    dwconv_rows_kernel<<<BATCH*192*32, 256>>>(qkv1, w_dw_w, w_dw_b, qkv2, 192, 128);
    cudaMemsetAsync(attn, 0, (size_t)BATCH * WW * WW * sizeof(float));
    gram_kernel<0><<<dim3(2, 2, BATCH * KS), 256>>>(qkv2, qkv2 + 64*(long)HWD, attn, KS);
    softmax_kernel<<<dim3(WW, BATCH), 256>>>(attn, w_temp, nullptr, nullptr);
    // AV (mma3t): A=v bf16 [16384,256], B=attn fp32, C=bufA bf16
    mma3t_kernel<1,0,1, 256,256,256, 1><<<dim3(128, 2, BATCH), 256>>>(
        qkv2 + 128*(long)HWD, attn, bufA, CHROWS, 16,
        sQ,0, sAT,0, sX,0, nullptr);
    // proj + residual x -> bufM (fp32)
    mma2_kernel<1,0,1,0><<<dim3(1, 1024, BATCH), 128>>>(w_proj_w, bufA, bufM,
        64, 4, 64, HWD, HWD, 1, 0,0, sX,0, sX,0, w_proj_b, x, sX,0);

    // ================= attention (HxH) =================
    ln_kernel<<<(BATCH * HWD) / 256, 256>>>(bufM, h_ln_w, h_ln_b, bufA);
    mma2_kernel<1,0,1,1><<<dim3(3, 1024, BATCH), 128>>>(h_qkv_w, bufA, qkv1,
        192, 4, 64, HWD, HWD, 1, 0,0, sX,0, sQ,0, h_qkv_b, nullptr, 0,0);
    dwconv_rows_kernel<<<BATCH*192*32, 256>>>(qkv1, h_dw_w, h_dw_b, qkv2, 192, 0);
    hnorm_kernel<<<dim3(HH, BATCH), 256>>>(qkv2,                sq);
    hnorm_kernel<<<dim3(HH, BATCH), 256>>>(qkv2 + 64*(long)HWD, sk);
    cudaMemsetAsync(attn, 0, (size_t)BATCH * WW * WW * sizeof(float));
    gram_kernel<1><<<dim3(2, 2, BATCH * KS), 256>>>(qkv2, qkv2 + 64*(long)HWD, attn, KS);
    softmax_kernel<<<dim3(WW, BATCH), 256>>>(attn, h_temp, sq, sk);
    // AV (mma3t): per (b,c): A=attn fp32 [256,256], B=v bf16, C=bufA bf16
    mma3t_kernel<0,1,1, 256,256,256, 64><<<dim3(2, 2, BATCH * 64), 256>>>(
        attn, qkv2 + 128*(long)HWD, bufA, 256, 16,
        sAT,0, sQ,(long)HWD, sX,(long)HWD, nullptr);
    // proj + residual m -> bufZ (fp32)
    mma2_kernel<1,0,1,0><<<dim3(1, 1024, BATCH), 128>>>(h_proj_w, bufA, bufZ,
        64, 4, 64, HWD, HWD, 1, 0,0, sX,0, sX,0, h_proj_b, bufM, sX,0);

    // ================= FFN =================
    ln_kernel<<<(BATCH * HWD) / 256, 256>>>(bufZ, n2_w, n2_b, bufA);
    // ffn_in (R10 config): A=W fp32 [340,64], B=ln bf16, C=qkv1 bf16
    mma2_kernel<2,0,1,1><<<dim3(3, 1024, BATCH), 128>>>(ffn_in_w, bufA, qkv1,
        HID2, 4, 64, HWD, HWD, 1, 0,0, sX,0, (long)HID2*HWD,0, ffn_in_b, nullptr, 0,0);
    dwconv_gate_kernel<<<BATCH*HID*32, 256>>>(qkv1, ffn_dw_w, ffn_dw_b, qkv2);
    // out = Wout(padded) @ gated(bf16) + bias + z (fp32 out)
    mma2_kernel<1,0,1,0><<<dim3(1, 1024, BATCH), 128>>>(wpad, qkv2, out,
        64, 11, 176, HWD, HWD, 1, 0,0, (long)HID*HWD,0, sX,0, ffn_out_b, bufZ, sX,0);
}

// round 17
// speedup vs baseline: 1.1702x; 1.0276x over previous
#include <cuda_runtime.h>
#include <cuda_bf16.h>
#include <math.h>

#define BATCH 4
#define CDIM  64
#define HH    256
#define WW    256
#define HWD   65536          // H*W
#define CHROWS 16384         // C*H
#define HID   170
#define HID2  340

// ---------------- scratch (device globals; no allocations allowed) ----------------
__device__ __nv_bfloat16 g_bufA[(size_t)BATCH * CDIM * HWD];   // ln out / AV out (bf16)
__device__ float         g_bufM[(size_t)BATCH * CDIM * HWD];   // wxw output (fp32)
__device__ float         g_bufZ[(size_t)BATCH * CDIM * HWD];   // hxh output (fp32)
__device__ __nv_bfloat16 g_qkv1[(size_t)BATCH * HID2 * HWD];
__device__ __nv_bfloat16 g_qkv2[(size_t)BATCH * HID2 * HWD];
__device__ float         g_attn[(size_t)BATCH * WW * WW + BATCH * 512]; // attn | ssq
__device__ float g_wpad[64 * 176];

// ---------------- helpers ----------------
__device__ __forceinline__ void mma8(float* d, unsigned a0, unsigned a1, unsigned a2, unsigned a3,
                                     unsigned b0, unsigned b1) {
    asm volatile(
        "mma.sync.aligned.m16n8k8.row.col.f32.tf32.tf32.f32 "
        "{%0,%1,%2,%3},{%4,%5,%6,%7},{%8,%9},{%0,%1,%2,%3};\n"
        : "+f"(d[0]), "+f"(d[1]), "+f"(d[2]), "+f"(d[3])
        : "r"(a0), "r"(a1), "r"(a2), "r"(a3), "r"(b0), "r"(b1));
}
#define CPA16(dst_u32, src_ptr) \
    asm volatile("cp.async.cg.shared.global [%0], [%1], 16;" :: "r"(dst_u32), "l"(src_ptr))

// ---------------- LayerNorm over channel dim (per pixel), single-read, bf16 out -------
__global__ void ln_kernel(const float* __restrict__ x, const float* __restrict__ w,
                          const float* __restrict__ b, __nv_bfloat16* __restrict__ y)
{
    long p = (long)blockIdx.x * blockDim.x + threadIdx.x;
    if (p >= (long)BATCH * HWD) return;
    int bb  = (int)(p >> 16);
    int pix = (int)(p & (HWD - 1));
    const float* xp = x + (long)bb * CDIM * HWD + pix;
    float v[64];
    float s = 0.f, s2 = 0.f;
#pragma unroll
    for (int c = 0; c < CDIM; c++) {
        float t = xp[(long)c * HWD];
        v[c] = t; s += t; s2 += t * t;
    }
    float mu  = s * (1.0f / CDIM);
    float var = s2 * (1.0f / CDIM) - mu * mu;
    float inv = rsqrtf(var + 1e-5f);
    __nv_bfloat16* yp = y + (long)bb * CDIM * HWD + pix;
#pragma unroll
    for (int c = 0; c < CDIM; c++)
        yp[(long)c * HWD] = __float2bfloat16((v[c] - mu) * inv * w[c] + b[c]);
}

// ---------------- pad ffn_out weight 64x170 -> 64x176 (zero fill) ----------------
__global__ void padw_kernel(const float* __restrict__ w, float* __restrict__ wp)
{
    int i = blockIdx.x * 256 + threadIdx.x;
    if (i >= 64 * 176) return;
    int r = i / 176, c = i - r * 176;
    wp[i] = (c < 170) ? w[r * 170 + c] : 0.f;
}

// ---------------- depthwise 3x3, warp-per-row, shuffle halos, bf16 io -----------------
// If c < normCh: in-place row L2 normalize (wxw q,k). If ssq != null and c < 2*CDIM:
// atomicAdd row sumsq into ssq[(b*2 + (c>=CDIM))*HH + h]  (hxh q,k norms).
__global__ void dwconv_rows_kernel(const __nv_bfloat16* __restrict__ x,
                                   const float* __restrict__ wt,
                                   const float* __restrict__ bias,
                                   __nv_bfloat16* __restrict__ y,
                                   int OC, int normCh, float* __restrict__ ssq)
{
    long bidx = blockIdx.x;
    int hb = (int)(bidx & 31) * 8;
    long bc = bidx >> 5;
    int c = (int)(bc % OC);
    int b = (int)(bc / OC);
    int warp = threadIdx.x >> 5, lane = threadIdx.x & 31;
    int h = hb + warp;
    const __nv_bfloat16* xp = x + (bc << 16);
    float b0 = bias[c];
    float acc[8];
#pragma unroll
    for (int j = 0; j < 8; j++) acc[j] = b0;
    const float* wc = wt + c * 9;
#pragma unroll
    for (int kh = -1; kh <= 1; kh++) {
        int hh = h + kh;
        if (hh < 0 || hh >= HH) continue;
        const uint4* rowp = reinterpret_cast<const uint4*>(xp + hh * WW);
        uint4 raw = rowp[lane];
        const __nv_bfloat16* hp = reinterpret_cast<const __nv_bfloat16*>(&raw);
        float vv[8];
#pragma unroll
        for (int j = 0; j < 8; j++) vv[j] = __bfloat162float(hp[j]);
        float vm1 = __shfl_up_sync(0xffffffffu, vv[7], 1);
        if (lane == 0) vm1 = 0.f;
        float vp8 = __shfl_down_sync(0xffffffffu, vv[0], 1);
        if (lane == 31) vp8 = 0.f;
        float vals[10] = {vm1, vv[0], vv[1], vv[2], vv[3], vv[4], vv[5], vv[6], vv[7], vp8};
        const float* wr = wc + (kh + 1) * 3;
#pragma unroll
        for (int kw = 0; kw < 3; kw++) {
            float g = wr[kw];
#pragma unroll
            for (int j = 0; j < 8; j++)
                acc[j] = fmaf(g, vals[j + kw], acc[j]);
        }
    }
    if (c < normCh) {
        float s = 0.f;
#pragma unroll
        for (int j = 0; j < 8; j++) s += acc[j] * acc[j];
#pragma unroll
        for (int o = 16; o > 0; o >>= 1) s += __shfl_xor_sync(0xffffffffu, s, o);
        float inv = 1.f / fmaxf(sqrtf(s), 1e-12f);
#pragma unroll
        for (int j = 0; j < 8; j++) acc[j] *= inv;
    }
    if (ssq && c < 2 * CDIM) {
        float s = 0.f;
#pragma unroll
        for (int j = 0; j < 8; j++) s += acc[j] * acc[j];
#pragma unroll
        for (int o = 16; o > 0; o >>= 1) s += __shfl_xor_sync(0xffffffffu, s, o);
        if (lane == 0)
            atomicAdd(&ssq[((long)b * 2 + (c >= CDIM ? 1 : 0)) * HH + h], s);
    }
    uint4 outr;
    __nv_bfloat16* op = reinterpret_cast<__nv_bfloat16*>(&outr);
#pragma unroll
    for (int j = 0; j < 8; j++) op[j] = __float2bfloat16(acc[j]);
    reinterpret_cast<uint4*>(y + (bc << 16) + h * WW)[lane] = outr;
}

// ---------------- fused FFN depthwise 3x3 + GELU gate, warp-per-row, bf16 io ----------
__global__ void dwconv_gate_kernel(const __nv_bfloat16* __restrict__ x,
                                   const float* __restrict__ wt,
                                   const float* __restrict__ bias,
                                   __nv_bfloat16* __restrict__ g)
{
    long bidx = blockIdx.x;
    int hb = (int)(bidx & 31) * 8;
    long bc = bidx >> 5;            // b*HID + c
    int c = (int)(bc % HID);
    int b = (int)(bc / HID);
    int warp = threadIdx.x >> 5, lane = threadIdx.x & 31;
    int h = hb + warp;
    const __nv_bfloat16* xp1 = x + ((long)b * HID2 + c) * HWD;
    const __nv_bfloat16* xp2 = xp1 + (long)HID * HWD;
    float bb1 = bias[c], bb2 = bias[c + HID];
    float acc1[8], acc2[8];
#pragma unroll
    for (int j = 0; j < 8; j++) { acc1[j] = bb1; acc2[j] = bb2; }
    const float* w1 = wt + c * 9;
    const float* w2 = wt + (c + HID) * 9;
#pragma unroll
    for (int kh = -1; kh <= 1; kh++) {
        int hh = h + kh;
        if (hh < 0 || hh >= HH) continue;
#pragma unroll
        for (int half = 0; half < 2; half++) {
            const __nv_bfloat16* xp = half ? xp2 : xp1;
            float* ac = half ? acc2 : acc1;
            const float* wr0 = (half ? w2 : w1) + (kh + 1) * 3;
            uint4 raw = reinterpret_cast<const uint4*>(xp + hh * WW)[lane];
            const __nv_bfloat16* hp = reinterpret_cast<const __nv_bfloat16*>(&raw);
            float vv[8];
#pragma unroll
            for (int j = 0; j < 8; j++) vv[j] = __bfloat162float(hp[j]);
            float vm1 = __shfl_up_sync(0xffffffffu, vv[7], 1);
            if (lane == 0) vm1 = 0.f;
            float vp8 = __shfl_down_sync(0xffffffffu, vv[0], 1);
            if (lane == 31) vp8 = 0.f;
            float vals[10] = {vm1, vv[0], vv[1], vv[2], vv[3], vv[4], vv[5], vv[6], vv[7], vp8};
#pragma unroll
            for (int kw = 0; kw < 3; kw++) {
                float gg = wr0[kw];
#pragma unroll
                for (int j = 0; j < 8; j++)
                    ac[j] = fmaf(gg, vals[j + kw], ac[j]);
            }
        }
    }
    const float kk = 0.70710678118654752f;
    uint4 outr;
    __nv_bfloat16* op = reinterpret_cast<__nv_bfloat16*>(&outr);
#pragma unroll
    for (int j = 0; j < 8; j++)
        op[j] = __float2bfloat16(0.5f * acc1[j] * (1.0f + erff(acc1[j] * kk)) * acc2[j]);
    reinterpret_cast<uint4*>(g + ((long)b * HID + c) * HWD + h * WW)[lane] = outr;
}

// ---------------- softmax over last dim of [B,256,256]; optional fused hxh norms ------
// ssq layout: [b][2][256] raw sum-of-squares; scale = 1/max(sqrt(s),1e-12) per q row / k col.
__global__ void softmax_kernel(float* __restrict__ attn, const float* __restrict__ temp,
                               const float* __restrict__ ssq)
{
    int b = blockIdx.y;
    int r = blockIdx.x;
    float* row = attn + ((long)b * WW + r) * WW;
    int t = threadIdx.x;
    float v = row[t] * temp[0];
    if (ssq) {
        float rq = 1.f / fmaxf(sqrtf(ssq[b * 512 + r]), 1e-12f);
        float rk = 1.f / fmaxf(sqrtf(ssq[b * 512 + 256 + t]), 1e-12f);
        v *= rq * rk;
    }
    __shared__ float red[256];
    red[t] = v; __syncthreads();
    for (int o = 128; o > 0; o >>= 1) { if (t < o) red[t] = fmaxf(red[t], red[t + o]); __syncthreads(); }
    float mx = red[0]; __syncthreads();
    float e = __expf(v - mx);
    red[t] = e; __syncthreads();
    for (int o = 128; o > 0; o >>= 1) { if (t < o) red[t] += red[t + o]; __syncthreads(); }
    row[t] = e * (1.f / red[0]);
}

// ---------------- gram kernel, bf16 operands, fp32 atomic out (unchanged) -------------
template<int L>
__global__ void __launch_bounds__(256, 2) gram_kernel(
    const __nv_bfloat16* __restrict__ Qb, const __nv_bfloat16* __restrict__ Kb,
    float* __restrict__ Cb, int KS)
{
    constexpr int P0 = 136;
    constexpr int P1 = 24;
    constexpr int SSZ = (L == 0) ? 2 * 16 * P0 : 2 * 128 * P1;
    __shared__ __align__(16) __nv_bfloat16 As[SSZ];
    __shared__ __align__(16) __nv_bfloat16 Bs[SSZ];

    int z = blockIdx.z;
    int b = z / KS, ks = z - b * KS;
    const __nv_bfloat16* Q = Qb + (long)b * (3 * CDIM * HWD);
    const __nv_bfloat16* Kp = Kb + (long)b * (3 * CDIM * HWD);
    float* C = Cb + (long)b * 65536;
    int m0 = blockIdx.x * 128, n0 = blockIdx.y * 128;
    int kchunk = 16384 / KS;
    int kbeg = ks * kchunk, kend = kbeg + kchunk;

    int tid = threadIdx.x, lane = tid & 31, warp = tid >> 5;
    int wm = warp & 1, wn = warp >> 1;
    int r = lane >> 2, c = lane & 3;

    unsigned sA = (unsigned)__cvta_generic_to_shared(As);
    unsigned sB = (unsigned)__cvta_generic_to_shared(Bs);

    auto loadStage = [&](int buf, int k0) {
        if (L == 0) {
            int row = tid >> 4;
            int q   = tid & 15;
            const __nv_bfloat16* gA = Q  + (long)(k0 + row) * 256 + m0;
            const __nv_bfloat16* gB = Kp + (long)(k0 + row) * 256 + n0;
            unsigned dA = sA + ((buf * 16 + row) * P0) * 2;
            unsigned dB = sB + ((buf * 16 + row) * P0) * 2;
            CPA16(dA + q * 16, gA + q * 8);
            CPA16(dB + q * 16, gB + q * 8);
        } else {
            int m  = tid >> 1;
            int qi = tid & 1;
            long kb = (long)(k0 >> 8) * 65536 + (k0 & 255);
            const __nv_bfloat16* gA = Q  + (long)(m0 + m) * 256 + kb;
            const __nv_bfloat16* gB = Kp + (long)(n0 + m) * 256 + kb;
            unsigned dA = sA + ((buf * 128 + m) * P1) * 2;
            unsigned dB = sB + ((buf * 128 + m) * P1) * 2;
            CPA16(dA + qi * 16, gA + qi * 8);
            CPA16(dB + qi * 16, gB + qi * 8);
        }
    };

    float acc[16][4];
#pragma unroll
    for (int i = 0; i < 16; i++)
#pragma unroll
        for (int j = 0; j < 4; j++) acc[i][j] = 0.f;

    loadStage(0, kbeg);
    asm volatile("cp.async.commit_group;");
    int buf = 0;

    for (int k0 = kbeg; k0 < kend; k0 += 16) {
        int kn = k0 + 16;
        if (kn < kend) loadStage(buf ^ 1, kn);
        asm volatile("cp.async.commit_group;");
        asm volatile("cp.async.wait_group 1;");
        __syncthreads();

        const __nv_bfloat16* A_ = As + (L == 0 ? buf * 16 * P0 : buf * 128 * P1);
        const __nv_bfloat16* B_ = Bs + (L == 0 ? buf * 16 * P0 : buf * 128 * P1);
#pragma unroll
        for (int ks2 = 0; ks2 < 2; ks2++) {
            int kc = ks2 * 8 + c;
            unsigned a0[4], a1[4], a2[4], a3[4];
#pragma unroll
            for (int mt = 0; mt < 4; mt++) {
                int mr = wm * 64 + mt * 16 + r;
                if (L == 0) {
                    a0[mt] = __float_as_uint(__bfloat162float(A_[kc * P0 + mr]));
                    a1[mt] = __float_as_uint(__bfloat162float(A_[kc * P0 + mr + 8]));
                    a2[mt] = __float_as_uint(__bfloat162float(A_[(kc + 4) * P0 + mr]));
                    a3[mt] = __float_as_uint(__bfloat162float(A_[(kc + 4) * P0 + mr + 8]));
                } else {
                    a0[mt] = __float_as_uint(__bfloat162float(A_[mr * P1 + kc]));
                    a1[mt] = __float_as_uint(__bfloat162float(A_[(mr + 8) * P1 + kc]));
                    a2[mt] = __float_as_uint(__bfloat162float(A_[mr * P1 + kc + 4]));
                    a3[mt] = __float_as_uint(__bfloat162float(A_[(mr + 8) * P1 + kc + 4]));
                }
            }
#pragma unroll
            for (int j = 0; j < 4; j++) {
                int nn = wn * 32 + j * 8 + r;
                unsigned b0, b1;
                if (L == 0) {
                    b0 = __float_as_uint(__bfloat162float(B_[kc * P0 + nn]));
                    b1 = __float_as_uint(__bfloat162float(B_[(kc + 4) * P0 + nn]));
                } else {
                    b0 = __float_as_uint(__bfloat162float(B_[nn * P1 + kc]));
                    b1 = __float_as_uint(__bfloat162float(B_[nn * P1 + kc + 4]));
                }
#pragma unroll
                for (int mt = 0; mt < 4; mt++)
                    mma8(acc[mt * 4 + j], a0[mt], a1[mt], a2[mt], a3[mt], b0, b1);
            }
        }
        __syncthreads();
        buf ^= 1;
    }

#pragma unroll
    for (int mt = 0; mt < 4; mt++) {
#pragma unroll
        for (int j = 0; j < 4; j++) {
            int mrow = m0 + wm * 64 + mt * 16 + r;
            int n    = n0 + wn * 32 + j * 8 + c * 2;
            float* ci = acc[mt * 4 + j];
            atomicAdd(&C[(long)mrow * 256 + n],           ci[0]);
            atomicAdd(&C[(long)mrow * 256 + n + 1],       ci[1]);
            atomicAdd(&C[(long)(mrow + 8) * 256 + n],     ci[2]);
            atomicAdd(&C[(long)(mrow + 8) * 256 + n + 1], ci[3]);
        }
    }
}

// ---------------- mma2 (R10-proven): BM=MT*64, BN=64, 128 thr, mixed dtypes -----------
template<int MT, int ABF, int BBF, int CBF>
__global__ void __launch_bounds__(128, (MT == 1) ? 4 : 3) mma2_kernel(
    const void* __restrict__ Av, const void* __restrict__ Bv, void* __restrict__ Cv,
    int M, int kit16, int lda, long sbk, int ldc, int zdiv,
    long sA1, long sA2, long sB1, long sB2, long sC1, long sC2,
    const float* __restrict__ bias,
    const float* __restrict__ res, long sR1, long sR2)
{
    constexpr int BM = MT * 64;
    constexpr int PA = ABF ? 24 : 20;
    constexpr int PB = BBF ? 72 : 68;
    constexpr int esA = ABF ? 2 : 4;
    constexpr int esB = BBF ? 2 : 4;
    constexpr int esC = CBF ? 2 : 4;
    constexpr int EA = ABF ? 8 : 4;
    constexpr int EB = BBF ? 8 : 4;
    constexpr int cprA = 16 / EA;
    constexpr int cprB = 64 / EB;
    __shared__ __align__(16) char AsRaw[2 * BM * PA * esA];
    __shared__ __align__(16) char BsRaw[2 * 16 * PB * esB];

    int z = blockIdx.z;
    int z1 = z / zdiv, z2 = z - z1 * zdiv;
    const char* Apc = (const char*)Av + ((long)z1 * sA1 + (long)z2 * sA2) * esA;
    const char* Bpc = (const char*)Bv + ((long)z1 * sB1 + (long)z2 * sB2) * esB;
    char*       Cpc = (char*)Cv + ((long)z1 * sC1 + (long)z2 * sC2) * esC;

    int m0 = blockIdx.x * BM;
    int n0 = blockIdx.y * 64;

    int tid = threadIdx.x, lane = tid & 31, warp = tid >> 5;
    int r = lane >> 2, c = lane & 3;

    unsigned sAu = (unsigned)__cvta_generic_to_shared(AsRaw);
    unsigned sBu = (unsigned)__cvta_generic_to_shared(BsRaw);

    auto loadStage = [&](int buf, int kit) {
        int k0 = kit * 16;
#pragma unroll
        for (int i = 0; i < BM * cprA / 128; i++) {
            int q = tid + i * 128;
            int m = q / cprA, sub = q - m * cprA;
            int gm = min(m0 + m, M - 1);
            CPA16(sAu + ((buf * BM + m) * PA + sub * EA) * esA,
                  Apc + ((long)gm * lda + k0 + sub * EA) * esA);
        }
#pragma unroll
        for (int i = 0; i < 16 * cprB / 128; i++) {
            int q = tid + i * 128;
            int k = q / cprB, sub = q - k * cprB;
            CPA16(sBu + ((buf * 16 + k) * PB + sub * EB) * esB,
                  Bpc + ((long)(k0 + k) * sbk + n0 + sub * EB) * esB);
        }
    };

    float acc[MT * 8][4];
#pragma unroll
    for (int i = 0; i < MT * 8; i++)
#pragma unroll
        for (int j = 0; j < 4; j++) acc[i][j] = 0.f;

    loadStage(0, 0);
    asm volatile("cp.async.commit_group;");
    int buf = 0;

    for (int kit = 0; kit < kit16; kit++) {
        if (kit + 1 < kit16) loadStage(buf ^ 1, kit + 1);
        asm volatile("cp.async.commit_group;");
        asm volatile("cp.async.wait_group 1;");
        __syncthreads();

        const char* A_ = AsRaw + buf * BM * PA * esA;
        const char* B_ = BsRaw + buf * 16 * PB * esB;
        auto ldA = [&](int idx) -> unsigned {
            if (ABF) return __float_as_uint(__bfloat162float(((const __nv_bfloat16*)A_)[idx]));
            return __float_as_uint(((const float*)A_)[idx]);
        };
        auto ldB = [&](int idx) -> unsigned {
            if (BBF) return __float_as_uint(__bfloat162float(((const __nv_bfloat16*)B_)[idx]));
            return __float_as_uint(((const float*)B_)[idx]);
        };
#pragma unroll
        for (int ks2 = 0; ks2 < 2; ks2++) {
            int kc = ks2 * 8 + c;
            unsigned a0[MT], a1[MT], a2[MT], a3[MT];
#pragma unroll
            for (int mt = 0; mt < MT; mt++) {
                int mr = warp * (MT * 16) + mt * 16 + r;
                a0[mt] = ldA(mr * PA + kc);
                a1[mt] = ldA((mr + 8) * PA + kc);
                a2[mt] = ldA(mr * PA + kc + 4);
                a3[mt] = ldA((mr + 8) * PA + kc + 4);
            }
#pragma unroll
            for (int j = 0; j < 8; j++) {
                int nn = j * 8 + r;
                unsigned b0 = ldB(kc * PB + nn);
                unsigned b1 = ldB((kc + 4) * PB + nn);
#pragma unroll
                for (int mt = 0; mt < MT; mt++)
                    mma8(acc[mt * 8 + j], a0[mt], a1[mt], a2[mt], a3[mt], b0, b1);
            }
        }
        __syncthreads();
        buf ^= 1;
    }

    const float* Rp = res ? res + (long)z1 * sR1 + (long)z2 * sR2 : nullptr;
#pragma unroll
    for (int mt = 0; mt < MT; mt++) {
#pragma unroll
        for (int j = 0; j < 8; j++) {
            int mA = m0 + warp * (MT * 16) + mt * 16 + r;
            int n  = n0 + j * 8 + c * 2;
            float* ci = acc[mt * 8 + j];
#pragma unroll
            for (int half = 0; half < 2; half++) {
                int mrow = mA + half * 8;
                if (mrow >= M) continue;
                float bv = bias ? bias[mrow] : 0.f;
                float v0 = ci[half * 2 + 0] + bv;
                float v1 = ci[half * 2 + 1] + bv;
                long off = (long)mrow * ldc + n;
                if (Rp) { v0 += Rp[off]; v1 += Rp[off + 1]; }
                if (CBF) {
                    __nv_bfloat162 h = __floats2bfloat162_rn(v0, v1);
                    *reinterpret_cast<__nv_bfloat162*>(Cpc + off * 2) = h;
                } else {
                    *reinterpret_cast<float2*>(Cpc + off * 4) = make_float2(v0, v1);
                }
            }
        }
    }
}

// ---------------- projln: proj GEMM (64x64xHWD) + residual + fused next-LayerNorm -----
// C[ch,p] = sum_k W[ch,k]*B[k,p] + bias[ch] + res[ch,p]  (fp32 out)
// lnout[ch,p] = LN_ch(C)[ch,p] * gam[ch] + bet[ch]       (bf16, written into B's buffer)
// One block owns all 64 channels of 64 pixels. grid (HWD/64, BATCH), 128 threads.
__global__ void __launch_bounds__(128, 3) projln_kernel(
    const float* __restrict__ A, const __nv_bfloat16* __restrict__ B,
    float* __restrict__ C, const float* __restrict__ res,
    const float* __restrict__ bias,
    const float* __restrict__ gam, const float* __restrict__ bet,
    __nv_bfloat16* __restrict__ lnout)
{
    constexpr int PA = 20;
    constexpr int PB = 72;
    __shared__ __align__(16) float As[2 * 64 * PA];
    __shared__ __align__(16) __nv_bfloat16 Bs[2 * 16 * PB];
    __shared__ float s1[256], s2[256];

    long zoff = (long)blockIdx.y * (CDIM * (long)HWD);
    const __nv_bfloat16* Bp = B + zoff;
    float* Cp = C + zoff;
    const float* Rp = res + zoff;
    __nv_bfloat16* Lp = lnout + zoff;
    int n0 = blockIdx.x * 64;

    int tid = threadIdx.x, lane = tid & 31, warp = tid >> 5;
    int r = lane >> 2, c = lane & 3;

    unsigned sAu = (unsigned)__cvta_generic_to_shared(As);
    unsigned sBu = (unsigned)__cvta_generic_to_shared(Bs);

    auto loadStage = [&](int buf, int kit) {
        int k0 = kit * 16;
#pragma unroll
        for (int i = 0; i < 2; i++) {
            int q = tid + i * 128;
            int m = q >> 2, k4 = (q & 3) * 4;
            CPA16(sAu + ((buf * 64 + m) * PA + k4) * 4, A + m * 64 + k0 + k4);
        }
        int k = tid >> 3, sub = tid & 7;
        CPA16(sBu + ((buf * 16 + k) * PB + sub * 8) * 2,
              Bp + (long)(k0 + k) * HWD + n0 + sub * 8);
    };

    float acc[8][4];
#pragma unroll
    for (int i = 0; i < 8; i++)
#pragma unroll
        for (int j = 0; j < 4; j++) acc[i][j] = 0.f;

    loadStage(0, 0);
    asm volatile("cp.async.commit_group;");
    int buf = 0;

    for (int kit = 0; kit < 4; kit++) {
        if (kit + 1 < 4) loadStage(buf ^ 1, kit + 1);
        asm volatile("cp.async.commit_group;");
        asm volatile("cp.async.wait_group 1;");
        __syncthreads();

        const float* A_ = As + buf * 64 * PA;
        const __nv_bfloat16* B_ = Bs + buf * 16 * PB;
#pragma unroll
        for (int ks2 = 0; ks2 < 2; ks2++) {
            int kc = ks2 * 8 + c;
            int mr = warp * 16 + r;
            unsigned a0 = __float_as_uint(A_[mr * PA + kc]);
            unsigned a1 = __float_as_uint(A_[(mr + 8) * PA + kc]);
            unsigned a2 = __float_as_uint(A_[mr * PA + kc + 4]);
            unsigned a3 = __float_as_uint(A_[(mr + 8) * PA + kc + 4]);
#pragma unroll
            for (int j = 0; j < 8; j++) {
                int nn = j * 8 + r;
                unsigned b0 = __float_as_uint(__bfloat162float(B_[kc * PB + nn]));
                unsigned b1 = __float_as_uint(__bfloat162float(B_[(kc + 4) * PB + nn]));
                mma8(acc[j], a0, a1, a2, a3, b0, b1);
            }
        }
        __syncthreads();
        buf ^= 1;
    }

    // ---- epilogue: v = acc + bias + res; store fp32; column stats; LN; store bf16 ----
    float ps[16], pq[16];
#pragma unroll
    for (int i = 0; i < 16; i++) { ps[i] = 0.f; pq[i] = 0.f; }
    int row0 = warp * 16 + r;
    float bv0 = bias[row0], bv8 = bias[row0 + 8];
#pragma unroll
    for (int j = 0; j < 8; j++) {
        int ncol = j * 8 + c * 2;
#pragma unroll
        for (int half = 0; half < 2; half++) {
            int row = row0 + half * 8;
            float bv = half ? bv8 : bv0;
            long off = (long)row * HWD + n0 + ncol;
            float v0 = acc[j][half * 2 + 0] + bv + Rp[off];
            float v1 = acc[j][half * 2 + 1] + bv + Rp[off + 1];
            acc[j][half * 2 + 0] = v0;
            acc[j][half * 2 + 1] = v1;
            *reinterpret_cast<float2*>(&Cp[off]) = make_float2(v0, v1);
            ps[j * 2 + 0] += v0; ps[j * 2 + 1] += v1;
            pq[j * 2 + 0] += v0 * v0; pq[j * 2 + 1] += v1 * v1;
        }
    }
#pragma unroll
    for (int o = 4; o <= 16; o <<= 1) {
#pragma unroll
        for (int i = 0; i < 16; i++) {
            ps[i] += __shfl_xor_sync(0xffffffffu, ps[i], o);
            pq[i] += __shfl_xor_sync(0xffffffffu, pq[i], o);
        }
    }
    if (r == 0) {
#pragma unroll
        for (int j = 0; j < 8; j++) {
            int ncol = j * 8 + c * 2;
            s1[warp * 64 + ncol]     = ps[j * 2];
            s1[warp * 64 + ncol + 1] = ps[j * 2 + 1];
            s2[warp * 64 + ncol]     = pq[j * 2];
            s2[warp * 64 + ncol + 1] = pq[j * 2 + 1];
        }
    }
    __syncthreads();
    float g0 = gam[row0], g8 = gam[row0 + 8];
    float e0 = bet[row0], e8 = bet[row0 + 8];
#pragma unroll
    for (int j = 0; j < 8; j++) {
        int ncol = j * 8 + c * 2;
        float l00, l01, l80, l81;
#pragma unroll
        for (int d = 0; d < 2; d++) {
            int col = ncol + d;
            float m1 = s1[col] + s1[64 + col] + s1[128 + col] + s1[192 + col];
            float m2 = s2[col] + s2[64 + col] + s2[128 + col] + s2[192 + col];
            float mean = m1 * (1.0f / 64.0f);
            float inv = rsqrtf(m2 * (1.0f / 64.0f) - mean * mean + 1e-5f);
            float v0 = (acc[j][0 + d] - mean) * inv;
            float v8 = (acc[j][2 + d] - mean) * inv;
            if (d == 0) { l00 = v0 * g0 + e0; l80 = v8 * g8 + e8; }
            else        { l01 = v0 * g0 + e0; l81 = v8 * g8 + e8; }
        }
        long off0 = (long)row0 * HWD + n0 + ncol;
        long off8 = (long)(row0 + 8) * HWD + n0 + ncol;
        *reinterpret_cast<__nv_bfloat162*>(&Lp[off0]) = __floats2bfloat162_rn(l00, l01);
        *reinterpret_cast<__nv_bfloat162*>(&Lp[off8]) = __floats2bfloat162_rn(l80, l81);
    }
}

extern "C" void kernel_launch(void* const* d_in, const int* in_sizes, int n_in,
                              void* d_out, int out_size)
{
    const float* x        = (const float*)d_in[0];
    const float* w_ln_w   = (const float*)d_in[2];
    const float* w_ln_b   = (const float*)d_in[3];
    const float* w_qkv_w  = (const float*)d_in[4];
    const float* w_qkv_b  = (const float*)d_in[5];
    const float* w_dw_w   = (const float*)d_in[6];
    const float* w_dw_b   = (const float*)d_in[7];
    const float* w_proj_w = (const float*)d_in[8];
    const float* w_proj_b = (const float*)d_in[9];
    const float* w_temp   = (const float*)d_in[10];
    const float* h_ln_w   = (const float*)d_in[11];
    const float* h_ln_b   = (const float*)d_in[12];
    const float* h_qkv_w  = (const float*)d_in[13];
    const float* h_qkv_b  = (const float*)d_in[14];
    const float* h_dw_w   = (const float*)d_in[15];
    const float* h_dw_b   = (const float*)d_in[16];
    const float* h_proj_w = (const float*)d_in[17];
    const float* h_proj_b = (const float*)d_in[18];
    const float* h_temp   = (const float*)d_in[19];
    const float* n2_w     = (const float*)d_in[20];
    const float* n2_b     = (const float*)d_in[21];
    const float* ffn_in_w = (const float*)d_in[22];
    const float* ffn_in_b = (const float*)d_in[23];
    const float* ffn_dw_w = (const float*)d_in[24];
    const float* ffn_dw_b = (const float*)d_in[25];
    const float* ffn_out_w= (const float*)d_in[26];
    const float* ffn_out_b= (const float*)d_in[27];
    float* out = (float*)d_out;

    __nv_bfloat16 *bufA, *qkv1, *qkv2;
    float *bufM, *bufZ, *attn, *wpad;
    cudaGetSymbolAddress((void**)&bufA, g_bufA);
    cudaGetSymbolAddress((void**)&bufM, g_bufM);
    cudaGetSymbolAddress((void**)&bufZ, g_bufZ);
    cudaGetSymbolAddress((void**)&qkv1, g_qkv1);
    cudaGetSymbolAddress((void**)&qkv2, g_qkv2);
    cudaGetSymbolAddress((void**)&attn, g_attn);
    cudaGetSymbolAddress((void**)&wpad, g_wpad);
    float* ssq = attn + (size_t)BATCH * WW * WW;   // [BATCH][2][256]

    const long sX = (long)CDIM * HWD;
    const long sQ = (long)3 * CDIM * HWD;
    const long sAT = (long)WW * WW;
    const int KS = 32;
    const size_t scrBytes = ((size_t)BATCH * WW * WW + BATCH * 512) * sizeof(float);

    padw_kernel<<<(64 * 176 + 255) / 256, 256>>>(ffn_out_w, wpad);

    // ================= attention (WxW) =================
    ln_kernel<<<(BATCH * HWD) / 256, 256>>>(x, w_ln_w, w_ln_b, bufA);
    mma2_kernel<1,0,1,1><<<dim3(3, 1024, BATCH), 128>>>(w_qkv_w, bufA, qkv1,
        192, 4, 64, HWD, HWD, 1, 0,0, sX,0, sQ,0, w_qkv_b, nullptr, 0,0);
    cudaMemsetAsync(attn, 0, scrBytes);
    dwconv_rows_kernel<<<BATCH*192*32, 256>>>(qkv1, w_dw_w, w_dw_b, qkv2, 192, 128, nullptr);
    gram_kernel<0><<<dim3(2, 2, BATCH * KS), 256>>>(qkv2, qkv2 + 64*(long)HWD, attn, KS);
    softmax_kernel<<<dim3(WW, BATCH), 256>>>(attn, w_temp, nullptr);
    mma2_kernel<2,1,0,1><<<dim3(128, 4, BATCH), 128>>>(qkv2 + 128*(long)HWD, attn, bufA,
        CHROWS, 16, 256, 256, 256, 1, sQ,0, sAT,0, sX,0, nullptr, nullptr, 0,0);
    // proj + residual x -> bufM (fp32), fused h-LayerNorm -> bufA (bf16)
    projln_kernel<<<dim3(1024, BATCH), 128>>>(w_proj_w, bufA, bufM, x, w_proj_b,
                                              h_ln_w, h_ln_b, bufA);

    // ================= attention (HxH) =================
    mma2_kernel<1,0,1,1><<<dim3(3, 1024, BATCH), 128>>>(h_qkv_w, bufA, qkv1,
        192, 4, 64, HWD, HWD, 1, 0,0, sX,0, sQ,0, h_qkv_b, nullptr, 0,0);
    cudaMemsetAsync(attn, 0, scrBytes);
    dwconv_rows_kernel<<<BATCH*192*32, 256>>>(qkv1, h_dw_w, h_dw_b, qkv2, 192, 0, ssq);
    gram_kernel<1><<<dim3(2, 2, BATCH * KS), 256>>>(qkv2, qkv2 + 64*(long)HWD, attn, KS);
    softmax_kernel<<<dim3(WW, BATCH), 256>>>(attn, h_temp, ssq);
    mma2_kernel<2,0,1,1><<<dim3(2, 4, BATCH * 64), 128>>>(attn, qkv2 + 128*(long)HWD, bufA,
        256, 16, 256, 256, 256, 64, sAT,0, sQ,(long)HWD, sX,(long)HWD,
        nullptr, nullptr, 0,0);
    // proj + residual m -> bufZ (fp32), fused n2-LayerNorm -> bufA (bf16)
    projln_kernel<<<dim3(1024, BATCH), 128>>>(h_proj_w, bufA, bufZ, bufM, h_proj_b,
                                              n2_w, n2_b, bufA);

    // ================= FFN =================
    mma2_kernel<2,0,1,1><<<dim3(3, 1024, BATCH), 128>>>(ffn_in_w, bufA, qkv1,
        HID2, 4, 64, HWD, HWD, 1, 0,0, sX,0, (long)HID2*HWD,0, ffn_in_b, nullptr, 0,0);
    dwconv_gate_kernel<<<BATCH*HID*32, 256>>>(qkv1, ffn_dw_w, ffn_dw_b, qkv2);
    mma2_kernel<1,0,1,0><<<dim3(1, 1024, BATCH), 128>>>(wpad, qkv2, out,
        64, 11, 176, HWD, HWD, 1, 0,0, (long)HID*HWD,0, sX,0, ffn_out_b, bufZ, sX,0);
}